// round 13
// baseline (speedup 1.0000x reference)
#include <cuda_runtime.h>
#include <cuda_bf16.h>
#include <cstdint>

namespace {
constexpr int B = 8;
constexpr int N = 2048;
constexpr int D = 128;
constexpr int LDS = 72;                    // padded smem row (bf16 elems)
constexpr int TILE_B = 128 * LDS * 2;      // 18432 bytes per operand tile
constexpr int STAGE_B = 4 * TILE_B;        // 73728: Ah, Al, Bh, Bl
constexpr int SMEM_MMA = 3 * STAGE_B;      // 221184
constexpr int ADJ_LDS = 132;               // fp32 elems per adj smem row
// fused_h dynamic smem: sW/sA2 (128*33) + max(sX, sA1)=32*129 + sH (32*129)
constexpr int FH_W  = 128 * 33;            // 4224 floats
constexpr int FH_B  = 32 * 129;            // 4128 floats
constexpr int SMEM_FH = (FH_W + 2 * FH_B) * 4;  // 49920 bytes
}

// ---------------------------------------------------------------------------
// Scratch (static device globals; no runtime allocation).
__device__ float g_hT[B * D * N];
__device__ float g_part[(size_t)B * N * 64];
__device__ __nv_bfloat16 g_hh[B * N * D];
__device__ __nv_bfloat16 g_hl[B * N * D];
__device__ __nv_bfloat16 g_Gh[B * N * D];  // splits of G = h.(A+A^T)
__device__ __nv_bfloat16 g_Gl[B * N * D];
__device__ __nv_bfloat16 g_sh[B * D * N];
__device__ __nv_bfloat16 g_sl[B * D * N];
__device__ __nv_bfloat16 g_Uh[(size_t)B * N * N];
__device__ __nv_bfloat16 g_Ul[(size_t)B * N * N];

// ---------------------------------------------------------------------------
__device__ __forceinline__ uint32_t smem_u32(const void* p) {
    uint32_t a;
    asm("{ .reg .u64 t; cvta.to.shared.u64 t, %1; cvt.u32.u64 %0, t; }" : "=r"(a) : "l"(p));
    return a;
}
__device__ __forceinline__ void cp16(uint32_t dst, const void* src) {
    asm volatile("cp.async.cg.shared.global [%0], [%1], 16;" :: "r"(dst), "l"(src));
}
#define CP_COMMIT() asm volatile("cp.async.commit_group;" ::: "memory")
#define CP_WAIT(n)  asm volatile("cp.async.wait_group %0;" :: "n"(n) : "memory")

__device__ __forceinline__ void issue_tile(uint32_t sdst,
                                           const __nv_bfloat16* __restrict__ base,
                                           size_t row0, int stride, int koff, int tid) {
#pragma unroll
    for (int t = 0; t < 4; t++) {
        const int i = t * 256 + tid;
        const int rr = i >> 3, c16 = i & 7;
        cp16(sdst + (uint32_t)(rr * LDS + c16 * 8) * 2,
             base + (row0 + rr) * (size_t)stride + koff + c16 * 8);
    }
}

__device__ __forceinline__ void adj_issue(uint32_t sdst, const float* __restrict__ adjb,
                                          int r0, int c0, int tid) {
#pragma unroll
    for (int t = 0; t < 16; t++) {
        const int i = t * 256 + tid;
        const int rr = i >> 5, cc = i & 31;
        cp16(sdst + (uint32_t)(rr * ADJ_LDS + cc * 4) * 4,
             adjb + (size_t)(r0 + rr) * N + c0 + cc * 4);
    }
    CP_COMMIT();
}

// ---------------------------------------------------------------------------
__device__ __forceinline__ void lda_frag(uint32_t sA, int wr, int mi, int kk, int lane,
                                         uint32_t (&a)[4]) {
    const uint32_t addr = sA +
        ((wr * 64 + mi * 16 + (lane & 15)) * LDS + kk * 16 + ((lane >> 4) << 3)) * 2;
    asm volatile("ldmatrix.sync.aligned.m8n8.x4.shared.b16 {%0,%1,%2,%3}, [%4];"
                 : "=r"(a[0]), "=r"(a[1]), "=r"(a[2]), "=r"(a[3]) : "r"(addr));
}
__device__ __forceinline__ void ldb_frag4(uint32_t sB, int wc, int p, int kk, int lane,
                                          uint32_t (&b0)[2], uint32_t (&b1)[2]) {
    const uint32_t addr = sB +
        ((wc * 32 + (2 * p + ((lane >> 4) & 1)) * 8 + (lane & 7)) * LDS +
         kk * 16 + (((lane >> 3) & 1) << 3)) * 2;
    asm volatile("ldmatrix.sync.aligned.m8n8.x4.shared.b16 {%0,%1,%2,%3}, [%4];"
                 : "=r"(b0[0]), "=r"(b0[1]), "=r"(b1[0]), "=r"(b1[1]) : "r"(addr));
}
__device__ __forceinline__ void mma16816(float (&d)[4], const uint32_t (&a)[4],
                                         const uint32_t (&b)[2]) {
    asm volatile(
        "mma.sync.aligned.m16n8k16.row.col.f32.bf16.bf16.f32 "
        "{%0,%1,%2,%3}, {%4,%5,%6,%7}, {%8,%9}, {%0,%1,%2,%3};"
        : "+f"(d[0]), "+f"(d[1]), "+f"(d[2]), "+f"(d[3])
        : "r"(a[0]), "r"(a[1]), "r"(a[2]), "r"(a[3]), "r"(b[0]), "r"(b[1]));
}

__device__ __forceinline__ void mma_tri(uint32_t sAh, uint32_t sAl,
                                        uint32_t sBh, uint32_t sBl,
                                        int wr, int wc, int lane,
                                        float (&acc)[4][4][4]) {
#pragma unroll
    for (int kk = 0; kk < 4; kk++) {
        uint32_t ah[4][4], al[4][4], bh[4][2], bl[4][2];
#pragma unroll
        for (int mi = 0; mi < 4; mi++) lda_frag(sAh, wr, mi, kk, lane, ah[mi]);
#pragma unroll
        for (int p = 0; p < 2; p++) ldb_frag4(sBh, wc, p, kk, lane, bh[2 * p], bh[2 * p + 1]);
#pragma unroll
        for (int mi = 0; mi < 4; mi++)
#pragma unroll
            for (int ni = 0; ni < 4; ni++) mma16816(acc[mi][ni], ah[mi], bh[ni]);
#pragma unroll
        for (int p = 0; p < 2; p++) ldb_frag4(sBl, wc, p, kk, lane, bl[2 * p], bl[2 * p + 1]);
#pragma unroll
        for (int mi = 0; mi < 4; mi++)
#pragma unroll
            for (int ni = 0; ni < 4; ni++) mma16816(acc[mi][ni], ah[mi], bl[ni]);
#pragma unroll
        for (int mi = 0; mi < 4; mi++) lda_frag(sAl, wr, mi, kk, lane, al[mi]);
#pragma unroll
        for (int mi = 0; mi < 4; mi++)
#pragma unroll
            for (int ni = 0; ni < 4; ni++) mma16816(acc[mi][ni], al[mi], bh[ni]);
    }
}

__device__ __forceinline__ void acc_to_smem(float* sD, int wr, int wc, int lane,
                                            const float (&acc)[4][4][4], bool do_exp) {
#pragma unroll
    for (int mi = 0; mi < 4; mi++)
#pragma unroll
        for (int ni = 0; ni < 4; ni++) {
            const int row = wr * 64 + mi * 16 + (lane >> 2);
            const int col = wc * 32 + ni * 8 + (lane & 3) * 2;
            if (do_exp) {
                sD[row * 129 + col]           = __expf(acc[mi][ni][0]);
                sD[row * 129 + col + 1]       = __expf(acc[mi][ni][1]);
                sD[(row + 8) * 129 + col]     = __expf(acc[mi][ni][2]);
                sD[(row + 8) * 129 + col + 1] = __expf(acc[mi][ni][3]);
            } else {
                sD[row * 129 + col]           = acc[mi][ni][0];
                sD[row * 129 + col + 1]       = acc[mi][ni][1];
                sD[(row + 8) * 129 + col]     = acc[mi][ni][2];
                sD[(row + 8) * 129 + col + 1] = acc[mi][ni][3];
            }
        }
}

__device__ __forceinline__ uint32_t pack_bf16(float a, float b) {
    const __nv_bfloat16 ha = __float2bfloat16_rn(a);
    const __nv_bfloat16 hb = __float2bfloat16_rn(b);
    uint32_t r;
    asm("mov.b32 %0, {%1, %2};" : "=r"(r)
        : "h"(*(const uint16_t*)&ha), "h"(*(const uint16_t*)&hb));
    return r;
}

// ---------------------------------------------------------------------------
// Fused front end (no prep kernel): h = x.W^T + b; G = h.(A+A^T);
// bf16 splits of both; hT fp32. W/A read in transposed-friendly layouts.
__global__ void __launch_bounds__(256) fused_h_k(
    const float* __restrict__ x, const float* __restrict__ W,
    const float* __restrict__ A, const float* __restrict__ bias) {
    extern __shared__ float fsm[];
    float* sW = fsm;                 // [128][33]  (W rows / A cols)
    float* sB = fsm + FH_W;          // phase A: sX [32][33]; phase B: sA1 [32][129]
    float* sH = fsm + FH_W + FH_B;   // [32][129]
    const int row0 = blockIdx.x * 32;
    const int b = row0 >> 11;
    const int n0 = row0 & (N - 1);
    const int tid = threadIdx.x;
    const int tc = tid & 15, tr = tid >> 4;
    float acc[2][8];

    // Phase A: h = x . W^T + bias   (h[r][col] = sum_k x[r][k] * W[col][k])
#pragma unroll
    for (int a = 0; a < 2; a++)
#pragma unroll
        for (int c = 0; c < 8; c++) acc[a][c] = 0.0f;
    for (int k0 = 0; k0 < D; k0 += 32) {
#pragma unroll
        for (int i = tid; i < 4096; i += 256) {
            const int cc = i >> 5, kk = i & 31;
            sW[cc * 33 + kk] = W[cc * D + k0 + kk];
        }
#pragma unroll
        for (int i = tid; i < 1024; i += 256)
            sB[(i >> 5) * 33 + (i & 31)] = x[(size_t)(row0 + (i >> 5)) * D + k0 + (i & 31)];
        __syncthreads();
#pragma unroll 8
        for (int kk = 0; kk < 32; kk++) {
            const float x0 = sB[tr * 33 + kk], x1 = sB[(tr + 16) * 33 + kk];
#pragma unroll
            for (int c = 0; c < 8; c++) {
                const float mv = sW[(tc + c * 16) * 33 + kk];
                acc[0][c] += x0 * mv;
                acc[1][c] += x1 * mv;
            }
        }
        __syncthreads();
    }
#pragma unroll
    for (int a = 0; a < 2; a++)
#pragma unroll
        for (int c = 0; c < 8; c++) {
            const int r = tr + a * 16, col = tc + c * 16;
            const float v = acc[a][c] + bias[col];
            sH[r * 129 + col] = v;
            const __nv_bfloat16 hi = __float2bfloat16_rn(v);
            const size_t o = (size_t)(row0 + r) * D + col;
            g_hh[o] = hi;
            g_hl[o] = __float2bfloat16_rn(v - __bfloat162float(hi));
        }
    __syncthreads();

    // Phase B: G = h . (A + A^T)
    // G[r][col] = sum_k h[r][k] * (A[k][col] + A[col][k])
#pragma unroll
    for (int a = 0; a < 2; a++)
#pragma unroll
        for (int c = 0; c < 8; c++) acc[a][c] = 0.0f;
    for (int k0 = 0; k0 < D; k0 += 32) {
#pragma unroll
        for (int i = tid; i < 4096; i += 256) {
            const int kk = i >> 7, cc = i & 127;
            sB[kk * 129 + cc] = A[(k0 + kk) * D + cc];     // sA1[kk][cc]
        }
#pragma unroll
        for (int i = tid; i < 4096; i += 256) {
            const int cc = i >> 5, kk = i & 31;
            sW[cc * 33 + kk] = A[cc * D + k0 + kk];        // sA2[cc][kk]
        }
        __syncthreads();
#pragma unroll 8
        for (int kk = 0; kk < 32; kk++) {
            const float x0 = sH[tr * 129 + k0 + kk], x1 = sH[(tr + 16) * 129 + k0 + kk];
#pragma unroll
            for (int c = 0; c < 8; c++) {
                const int col = tc + c * 16;
                const float mv = sB[kk * 129 + col] + sW[col * 33 + kk];
                acc[0][c] += x0 * mv;
                acc[1][c] += x1 * mv;
            }
        }
        __syncthreads();
    }
#pragma unroll
    for (int a = 0; a < 2; a++)
#pragma unroll
        for (int c = 0; c < 8; c++) {
            const int r = tr + a * 16, col = tc + c * 16;
            const float v = acc[a][c];
            const __nv_bfloat16 hi = __float2bfloat16_rn(v);
            const size_t o = (size_t)(row0 + r) * D + col;
            g_Gh[o] = hi;
            g_Gl[o] = __float2bfloat16_rn(v - __bfloat162float(hi));
        }

    // Phase C: hT fp32
    const int nn = tid & 31, d0 = tid >> 5;
#pragma unroll
    for (int dp = 0; dp < 16; dp++) {
        const int d = dp * 8 + d0;
        g_hT[((size_t)b * D + d) * N + n0 + nn] = sH[nn * 129 + d];
    }
}

// ---------------------------------------------------------------------------
// Esym = G.h^T (K=128, 2 chunks) over upper-triangle tile pairs.
__device__ __forceinline__ void esym_issue(int q, int stage, uint32_t sbase,
                                           size_t arow, size_t brow, int tid) {
    const int koff = q * 64;
    const uint32_t s = sbase + (uint32_t)stage * STAGE_B;
    issue_tile(s,              g_Gh, arow, D, koff, tid);
    issue_tile(s + TILE_B,     g_Gl, arow, D, koff, tid);
    issue_tile(s + 2 * TILE_B, g_hh, brow, D, koff, tid);
    issue_tile(s + 3 * TILE_B, g_hl, brow, D, koff, tid);
    CP_COMMIT();
}

__global__ void __launch_bounds__(256) esym_k(const float* __restrict__ adj) {
    extern __shared__ char sm[];
    const uint32_t sbase = smem_u32(sm);
    const int tid = threadIdx.x, wid = tid >> 5, lane = tid & 31;
    const int wr = wid >> 2, wc = wid & 3;

    int t = blockIdx.x % 136;
    const int b = blockIdx.x / 136;
    int tj = 0;
    while (t >= 16 - tj) { t -= 16 - tj; tj++; }
    const int tk = tj + t;
    const int j0 = tj * 128, k0 = tk * 128;
    const size_t arow = (size_t)b * N + j0, brow = (size_t)b * N + k0;
    const float* adjb = adj + (size_t)b * N * N;

    float acc[4][4][4];
#pragma unroll
    for (int mi = 0; mi < 4; mi++)
#pragma unroll
        for (int ni = 0; ni < 4; ni++)
#pragma unroll
            for (int q = 0; q < 4; q++) acc[mi][ni][q] = 0.0f;

    esym_issue(0, 0, sbase, arow, brow, tid);
    esym_issue(1, 1, sbase, arow, brow, tid);
    adj_issue(sbase + 2 * STAGE_B, adjb, j0, k0, tid);

    CP_WAIT(2); __syncthreads();
    mma_tri(sbase, sbase + TILE_B, sbase + 2 * TILE_B, sbase + 3 * TILE_B,
            wr, wc, lane, acc);
    __syncthreads();
    if (tj != tk) {
        adj_issue(sbase, adjb, k0, j0, tid);
        CP_WAIT(2);
    } else {
        CP_WAIT(1);
    }
    __syncthreads();
    {
        const uint32_t s = sbase + STAGE_B;
        mma_tri(s, s + TILE_B, s + 2 * TILE_B, s + 3 * TILE_B, wr, wc, lane, acc);
    }
    CP_WAIT(0);
    __syncthreads();

    float* sD  = (float*)(sm + STAGE_B);
    float* sA1 = (float*)(sm + 2 * STAGE_B);
    float* sA2 = (float*)sm;
    acc_to_smem(sD, wr, wc, lane, acc, true);
    __syncthreads();

    const int c2 = (tid & 63) * 2;
    const int p = tid >> 6;                // 0..3
    {
        float cs0 = 0.0f, cs1 = 0.0f;
        const size_t ub = (size_t)b * N * N + (size_t)j0 * N + k0;
#pragma unroll 8
        for (int it = 0; it < 32; it++) {
            const int r = it * 4 + p;
            const float v0 = (sA1[r * ADJ_LDS + c2] > 0.0f) ? sD[r * 129 + c2] : 0.0f;
            const float v1 = (sA1[r * ADJ_LDS + c2 + 1] > 0.0f) ? sD[r * 129 + c2 + 1] : 0.0f;
            const float h0 = __bfloat162float(__float2bfloat16_rn(v0));
            const float h1 = __bfloat162float(__float2bfloat16_rn(v1));
            const size_t o2 = (ub + (size_t)r * N + c2) >> 1;
            ((uint32_t*)g_Uh)[o2] = pack_bf16(v0, v1);
            ((uint32_t*)g_Ul)[o2] = pack_bf16(v0 - h0, v1 - h1);
            cs0 += v0;
            cs1 += v1;
        }
        g_part[((size_t)b * N + k0 + c2) * 64 + tj * 4 + p] = cs0;
        g_part[((size_t)b * N + k0 + c2 + 1) * 64 + tj * 4 + p] = cs1;
    }
    if (tj != tk) {
        float cs0 = 0.0f, cs1 = 0.0f;
        const size_t ub = (size_t)b * N * N + (size_t)k0 * N + j0;
#pragma unroll 8
        for (int it = 0; it < 32; it++) {
            const int r = it * 4 + p;
            const float v0 = (sA2[r * ADJ_LDS + c2] > 0.0f) ? sD[c2 * 129 + r] : 0.0f;
            const float v1 = (sA2[r * ADJ_LDS + c2 + 1] > 0.0f) ? sD[(c2 + 1) * 129 + r] : 0.0f;
            const float h0 = __bfloat162float(__float2bfloat16_rn(v0));
            const float h1 = __bfloat162float(__float2bfloat16_rn(v1));
            const size_t o2 = (ub + (size_t)r * N + c2) >> 1;
            ((uint32_t*)g_Uh)[o2] = pack_bf16(v0, v1);
            ((uint32_t*)g_Ul)[o2] = pack_bf16(v0 - h0, v1 - h1);
            cs0 += v0;
            cs1 += v1;
        }
        g_part[((size_t)b * N + j0 + c2) * 64 + tk * 4 + p] = cs0;
        g_part[((size_t)b * N + j0 + c2 + 1) * 64 + tk * 4 + p] = cs1;
    }
}

// ---------------------------------------------------------------------------
// Per block: reduce is[] for 256 columns, then scale 32 d-rows of hT; splits.
__global__ void __launch_bounds__(256) scale_is_k() {
    __shared__ float s_is[256];
    const int bx = blockIdx.x;
    const int b = bx >> 5;
    const int rem = bx & 31;
    const int j0 = (rem & 7) * 256;
    const int d0 = (rem >> 3) * 32;
    const int tid = threadIdx.x;

    {
        const float4* p = (const float4*)(g_part + ((size_t)b * N + j0 + tid) * 64);
        float s = 0.0f;
#pragma unroll
        for (int q = 0; q < 16; q++) {
            const float4 v = p[q];
            s += (v.x + v.y) + (v.z + v.w);
        }
        s_is[tid] = 1.0f / s;
    }
    __syncthreads();

    const int jq = tid & 63, dr0 = tid >> 6;
    const float4 sv = ((const float4*)s_is)[jq];
#pragma unroll
    for (int it = 0; it < 8; it++) {
        const int d = d0 + it * 4 + dr0;
        const size_t o4 = (((size_t)b * D + d) * N + j0) / 4 + jq;
        const float4 hv = ((const float4*)g_hT)[o4];
        const float v0 = hv.x * sv.x, v1 = hv.y * sv.y, v2 = hv.z * sv.z, v3 = hv.w * sv.w;
        const float h0 = __bfloat162float(__float2bfloat16_rn(v0));
        const float h1 = __bfloat162float(__float2bfloat16_rn(v1));
        const float h2 = __bfloat162float(__float2bfloat16_rn(v2));
        const float h3 = __bfloat162float(__float2bfloat16_rn(v3));
        uint2 ph, pl;
        ph.x = pack_bf16(v0, v1);
        ph.y = pack_bf16(v2, v3);
        pl.x = pack_bf16(v0 - h0, v1 - h1);
        pl.y = pack_bf16(v2 - h2, v3 - h3);
        ((uint2*)g_sh)[o4] = ph;
        ((uint2*)g_sl)[o4] = pl;
    }
}

// ---------------------------------------------------------------------------
// hp+gate fused: 32 chunks x 3 fused split terms; depth-2 prefetch on 3 stages.
__device__ __forceinline__ void hp_issue(int c, int stage, uint32_t sbase,
                                         size_t arow, size_t brow, int tid) {
    const int koff = c * 64;
    const uint32_t s = sbase + (uint32_t)stage * STAGE_B;
    issue_tile(s,              g_Uh, arow, N, koff, tid);
    issue_tile(s + TILE_B,     g_Ul, arow, N, koff, tid);
    issue_tile(s + 2 * TILE_B, g_sh, brow, N, koff, tid);
    issue_tile(s + 3 * TILE_B, g_sl, brow, N, koff, tid);
    CP_COMMIT();
}

__global__ void __launch_bounds__(256) hp_k(
    const float* __restrict__ x, const float* __restrict__ gw,
    const float* __restrict__ gb, float* __restrict__ out) {
    extern __shared__ char sm[];
    const uint32_t sbase = smem_u32(sm);
    const int tid = threadIdx.x, wid = tid >> 5, lane = tid & 31;
    const int wr = wid >> 2, wc = wid & 3;
    const int b = blockIdx.y;
    const int i0 = blockIdx.x * 128;
    const size_t arow = (size_t)b * N + i0;
    const size_t brow = (size_t)b * D;

    float acc[4][4][4];
#pragma unroll
    for (int mi = 0; mi < 4; mi++)
#pragma unroll
        for (int ni = 0; ni < 4; ni++)
#pragma unroll
            for (int q = 0; q < 4; q++) acc[mi][ni][q] = 0.0f;

    hp_issue(0, 0, sbase, arow, brow, tid);
    hp_issue(1, 1, sbase, arow, brow, tid);
#pragma unroll 1
    for (int c = 0; c < 32; c++) {
        if (c < 31) CP_WAIT(1);
        else CP_WAIT(0);
        __syncthreads();
        if (c + 2 < 32) hp_issue(c + 2, (c + 2) % 3, sbase, arow, brow, tid);
        const uint32_t s = sbase + (uint32_t)(c % 3) * STAGE_B;
        mma_tri(s, s + TILE_B, s + 2 * TILE_B, s + 3 * TILE_B, wr, wc, lane, acc);
    }
    __syncthreads();

    float* sD = (float*)sm;
    acc_to_smem(sD, wr, wc, lane, acc, false);
    __syncthreads();

    const float4 g1 = ((const float4*)gw)[lane];
    const float4 g2 = ((const float4*)(gw + D))[lane];
    const float gbv = gb[0];
#pragma unroll 1
    for (int rr = wid; rr < 128; rr += 8) {
        const size_t row = (size_t)b * N + i0 + rr;
        const float4 xv = ((const float4*)(x + row * D))[lane];
        float4 hv;
        hv.x = fmaxf(sD[rr * 129 + lane * 4 + 0], 0.0f);
        hv.y = fmaxf(sD[rr * 129 + lane * 4 + 1], 0.0f);
        hv.z = fmaxf(sD[rr * 129 + lane * 4 + 2], 0.0f);
        hv.w = fmaxf(sD[rr * 129 + lane * 4 + 3], 0.0f);
        float p = xv.x * g1.x + xv.y * g1.y + xv.z * g1.z + xv.w * g1.w
                + hv.x * g2.x + hv.y * g2.y + hv.z * g2.z + hv.w * g2.w;
#pragma unroll
        for (int o = 16; o > 0; o >>= 1) p += __shfl_xor_sync(0xffffffffu, p, o);
        const float cf = 1.0f / (1.0f + __expf(-(p + gbv)));
        const float df = 1.0f - cf;
        float4 o4;
        o4.x = cf * xv.x + df * hv.x;
        o4.y = cf * xv.y + df * hv.y;
        o4.z = cf * xv.z + df * hv.z;
        o4.w = cf * xv.w + df * hv.w;
        ((float4*)(out + row * D))[lane] = o4;
    }
}

// ---------------------------------------------------------------------------
extern "C" void kernel_launch(void* const* d_in, const int* in_sizes, int n_in,
                              void* d_out, int out_size) {
    const float* x   = (const float*)d_in[0];
    const float* adj = (const float*)d_in[1];
    const float* W_w = (const float*)d_in[2];
    const float* W_b = (const float*)d_in[3];
    const float* A   = (const float*)d_in[4];
    const float* gw  = (const float*)d_in[5];
    const float* gb  = (const float*)d_in[6];
    float* out = (float*)d_out;

    static bool attr_done = false;
    if (!attr_done) {
        cudaFuncSetAttribute(fused_h_k, cudaFuncAttributeMaxDynamicSharedMemorySize, SMEM_FH);
        cudaFuncSetAttribute(esym_k, cudaFuncAttributeMaxDynamicSharedMemorySize, SMEM_MMA);
        cudaFuncSetAttribute(hp_k,   cudaFuncAttributeMaxDynamicSharedMemorySize, SMEM_MMA);
        attr_done = true;
    }

    fused_h_k<<<(B * N) / 32, 256, SMEM_FH>>>(x, W_w, A, W_b);
    esym_k<<<B * 136, 256, SMEM_MMA>>>(adj);
    scale_is_k<<<B * 32, 256>>>();
    hp_k<<<dim3(N / 128, B), 256, SMEM_MMA>>>(x, gw, gb, out);
}

// round 14
// speedup vs baseline: 1.0884x; 1.0884x over previous
#include <cuda_runtime.h>
#include <cuda_bf16.h>
#include <cstdint>

namespace {
constexpr int B = 8;
constexpr int N = 2048;
constexpr int D = 128;
constexpr int LDS = 72;                    // padded smem row (bf16 elems)
constexpr int TILE_B = 128 * LDS * 2;      // 18432 bytes per operand tile
constexpr int STAGE_B = 4 * TILE_B;        // 73728: Ah, Al, Bh, Bl
constexpr int SMEM_MMA = 3 * STAGE_B;      // 221184
constexpr int ADJ_LDS = 132;               // fp32 elems per adj smem row
constexpr int NT = 512;                    // threads in MMA kernels
}

// ---------------------------------------------------------------------------
// Scratch (static device globals; no runtime allocation).
__device__ float g_Wt[D * D];
__device__ float g_M[D * D];               // A + A^T
__device__ float g_hT[B * D * N];
__device__ float g_part[(size_t)B * N * 128];
__device__ __nv_bfloat16 g_hh[B * N * D];
__device__ __nv_bfloat16 g_hl[B * N * D];
__device__ __nv_bfloat16 g_Gh[B * N * D];  // splits of G = h.(A+A^T)
__device__ __nv_bfloat16 g_Gl[B * N * D];
__device__ __nv_bfloat16 g_sh[B * D * N];
__device__ __nv_bfloat16 g_sl[B * D * N];
__device__ __nv_bfloat16 g_Uh[(size_t)B * N * N];
__device__ __nv_bfloat16 g_Ul[(size_t)B * N * N];

// ---------------------------------------------------------------------------
__device__ __forceinline__ uint32_t smem_u32(const void* p) {
    uint32_t a;
    asm("{ .reg .u64 t; cvta.to.shared.u64 t, %1; cvt.u32.u64 %0, t; }" : "=r"(a) : "l"(p));
    return a;
}
__device__ __forceinline__ void cp16(uint32_t dst, const void* src) {
    asm volatile("cp.async.cg.shared.global [%0], [%1], 16;" :: "r"(dst), "l"(src));
}
#define CP_COMMIT() asm volatile("cp.async.commit_group;" ::: "memory")
#define CP_WAIT(n)  asm volatile("cp.async.wait_group %0;" :: "n"(n) : "memory")

// 512-thread tile loader: 128x64 bf16 tile, 2 x 16B per thread.
__device__ __forceinline__ void issue_tile(uint32_t sdst,
                                           const __nv_bfloat16* __restrict__ base,
                                           size_t row0, int stride, int koff, int tid) {
#pragma unroll
    for (int t = 0; t < 2; t++) {
        const int i = t * NT + tid;
        const int rr = i >> 3, c16 = i & 7;
        cp16(sdst + (uint32_t)(rr * LDS + c16 * 8) * 2,
             base + (row0 + rr) * (size_t)stride + koff + c16 * 8);
    }
}

// 512-thread adj loader: 128x128 fp32 tile (row stride ADJ_LDS floats).
__device__ __forceinline__ void adj_issue(uint32_t sdst, const float* __restrict__ adjb,
                                          int r0, int c0, int tid) {
#pragma unroll
    for (int t = 0; t < 8; t++) {
        const int i = t * NT + tid;
        const int rr = i >> 5, cc = i & 31;
        cp16(sdst + (uint32_t)(rr * ADJ_LDS + cc * 4) * 4,
             adjb + (size_t)(r0 + rr) * N + c0 + cc * 4);
    }
    CP_COMMIT();
}

// ---------------------------------------------------------------------------
// Fragment loaders for the m16n8k16 layout. Warp tile 32(m) x 32(n).
__device__ __forceinline__ void lda_frag(uint32_t sA, int wr, int mi, int kk, int lane,
                                         uint32_t (&a)[4]) {
    const uint32_t addr = sA +
        ((wr * 32 + mi * 16 + (lane & 15)) * LDS + kk * 16 + ((lane >> 4) << 3)) * 2;
    asm volatile("ldmatrix.sync.aligned.m8n8.x4.shared.b16 {%0,%1,%2,%3}, [%4];"
                 : "=r"(a[0]), "=r"(a[1]), "=r"(a[2]), "=r"(a[3]) : "r"(addr));
}
__device__ __forceinline__ void ldb_frag4(uint32_t sB, int wc, int p, int kk, int lane,
                                          uint32_t (&b0)[2], uint32_t (&b1)[2]) {
    const uint32_t addr = sB +
        ((wc * 32 + (2 * p + ((lane >> 4) & 1)) * 8 + (lane & 7)) * LDS +
         kk * 16 + (((lane >> 3) & 1) << 3)) * 2;
    asm volatile("ldmatrix.sync.aligned.m8n8.x4.shared.b16 {%0,%1,%2,%3}, [%4];"
                 : "=r"(b0[0]), "=r"(b0[1]), "=r"(b1[0]), "=r"(b1[1]) : "r"(addr));
}
__device__ __forceinline__ void mma16816(float (&d)[4], const uint32_t (&a)[4],
                                         const uint32_t (&b)[2]) {
    asm volatile(
        "mma.sync.aligned.m16n8k16.row.col.f32.bf16.bf16.f32 "
        "{%0,%1,%2,%3}, {%4,%5,%6,%7}, {%8,%9}, {%0,%1,%2,%3};"
        : "+f"(d[0]), "+f"(d[1]), "+f"(d[2]), "+f"(d[3])
        : "r"(a[0]), "r"(a[1]), "r"(a[2]), "r"(a[3]), "r"(b[0]), "r"(b[1]));
}

// Three-term split MMA over one 64-wide K chunk; warp tile 32x32.
// acc += Ah.Bh + Ah.Bl + Al.Bh
__device__ __forceinline__ void mma_tri(uint32_t sAh, uint32_t sAl,
                                        uint32_t sBh, uint32_t sBl,
                                        int wr, int wc, int lane,
                                        float (&acc)[2][4][4]) {
#pragma unroll
    for (int kk = 0; kk < 4; kk++) {
        uint32_t ah[2][4], al[2][4], bh[4][2], bl[4][2];
#pragma unroll
        for (int mi = 0; mi < 2; mi++) lda_frag(sAh, wr, mi, kk, lane, ah[mi]);
#pragma unroll
        for (int p = 0; p < 2; p++) ldb_frag4(sBh, wc, p, kk, lane, bh[2 * p], bh[2 * p + 1]);
#pragma unroll
        for (int mi = 0; mi < 2; mi++)
#pragma unroll
            for (int ni = 0; ni < 4; ni++) mma16816(acc[mi][ni], ah[mi], bh[ni]);
#pragma unroll
        for (int p = 0; p < 2; p++) ldb_frag4(sBl, wc, p, kk, lane, bl[2 * p], bl[2 * p + 1]);
#pragma unroll
        for (int mi = 0; mi < 2; mi++)
#pragma unroll
            for (int ni = 0; ni < 4; ni++) mma16816(acc[mi][ni], ah[mi], bl[ni]);
#pragma unroll
        for (int mi = 0; mi < 2; mi++) lda_frag(sAl, wr, mi, kk, lane, al[mi]);
#pragma unroll
        for (int mi = 0; mi < 2; mi++)
#pragma unroll
            for (int ni = 0; ni < 4; ni++) mma16816(acc[mi][ni], al[mi], bh[ni]);
    }
}

__device__ __forceinline__ void acc_to_smem(float* sD, int wr, int wc, int lane,
                                            const float (&acc)[2][4][4], bool do_exp) {
#pragma unroll
    for (int mi = 0; mi < 2; mi++)
#pragma unroll
        for (int ni = 0; ni < 4; ni++) {
            const int row = wr * 32 + mi * 16 + (lane >> 2);
            const int col = wc * 32 + ni * 8 + (lane & 3) * 2;
            if (do_exp) {
                sD[row * 129 + col]           = __expf(acc[mi][ni][0]);
                sD[row * 129 + col + 1]       = __expf(acc[mi][ni][1]);
                sD[(row + 8) * 129 + col]     = __expf(acc[mi][ni][2]);
                sD[(row + 8) * 129 + col + 1] = __expf(acc[mi][ni][3]);
            } else {
                sD[row * 129 + col]           = acc[mi][ni][0];
                sD[row * 129 + col + 1]       = acc[mi][ni][1];
                sD[(row + 8) * 129 + col]     = acc[mi][ni][2];
                sD[(row + 8) * 129 + col + 1] = acc[mi][ni][3];
            }
        }
}

__device__ __forceinline__ uint32_t pack_bf16(float a, float b) {
    const __nv_bfloat16 ha = __float2bfloat16_rn(a);
    const __nv_bfloat16 hb = __float2bfloat16_rn(b);
    uint32_t r;
    asm("mov.b32 %0, {%1, %2};" : "=r"(r)
        : "h"(*(const uint16_t*)&ha), "h"(*(const uint16_t*)&hb));
    return r;
}

// ---------------------------------------------------------------------------
// Wt = W^T and M = A + A^T (both 128x128, tiny).
__global__ void prep_wm_k(const float* __restrict__ W, const float* __restrict__ A) {
    __shared__ float tw[32][33];
    __shared__ float ta[32][33];
    const int bx = blockIdx.x, by = blockIdx.y;
    const int x = bx * 32 + threadIdx.x;
    const int y0 = by * 32;
    for (int i = threadIdx.y; i < 32; i += 8) {
        tw[i][threadIdx.x] = W[(y0 + i) * D + x];
        ta[i][threadIdx.x] = A[(bx * 32 + i) * D + by * 32 + threadIdx.x];
    }
    __syncthreads();
    const int xo = by * 32 + threadIdx.x;
    const int yo0 = bx * 32;
    for (int i = threadIdx.y; i < 32; i += 8) {
        g_Wt[(yo0 + i) * D + xo] = tw[threadIdx.x][i];
        g_M[(y0 + i) * D + x] = A[(y0 + i) * D + x] + ta[threadIdx.x][i];
    }
}

// ---------------------------------------------------------------------------
// Fused front end: h = x.Wt + b; G = h.M; bf16 splits of both; hT fp32.
__global__ void __launch_bounds__(256) fused_h_k(const float* __restrict__ x,
                                                 const float* __restrict__ bias) {
    __shared__ float sM[32][D + 1];
    __shared__ float sX[32][33];
    __shared__ float sH[32][D + 1];
    const int row0 = blockIdx.x * 32;
    const int b = row0 >> 11;
    const int n0 = row0 & (N - 1);
    const int tid = threadIdx.x;
    const int tc = tid & 15, tr = tid >> 4;
    float acc[2][8];

#pragma unroll
    for (int a = 0; a < 2; a++)
#pragma unroll
        for (int c = 0; c < 8; c++) acc[a][c] = 0.0f;
    for (int k0 = 0; k0 < D; k0 += 32) {
#pragma unroll
        for (int i = tid; i < 32 * D; i += 256)
            sM[i >> 7][i & 127] = g_Wt[(k0 + (i >> 7)) * D + (i & 127)];
#pragma unroll
        for (int i = tid; i < 1024; i += 256)
            sX[i >> 5][i & 31] = x[(size_t)(row0 + (i >> 5)) * D + k0 + (i & 31)];
        __syncthreads();
#pragma unroll 8
        for (int kk = 0; kk < 32; kk++) {
            float x0 = sX[tr][kk], x1 = sX[tr + 16][kk];
#pragma unroll
            for (int c = 0; c < 8; c++) {
                float mv = sM[kk][tc + c * 16];
                acc[0][c] += x0 * mv;
                acc[1][c] += x1 * mv;
            }
        }
        __syncthreads();
    }
#pragma unroll
    for (int a = 0; a < 2; a++)
#pragma unroll
        for (int c = 0; c < 8; c++) {
            const int r = tr + a * 16, col = tc + c * 16;
            const float v = acc[a][c] + bias[col];
            sH[r][col] = v;
            const __nv_bfloat16 hi = __float2bfloat16_rn(v);
            const size_t o = (size_t)(row0 + r) * D + col;
            g_hh[o] = hi;
            g_hl[o] = __float2bfloat16_rn(v - __bfloat162float(hi));
        }
    __syncthreads();

#pragma unroll
    for (int a = 0; a < 2; a++)
#pragma unroll
        for (int c = 0; c < 8; c++) acc[a][c] = 0.0f;
    for (int k0 = 0; k0 < D; k0 += 32) {
#pragma unroll
        for (int i = tid; i < 32 * D; i += 256)
            sM[i >> 7][i & 127] = g_M[(k0 + (i >> 7)) * D + (i & 127)];
        __syncthreads();
#pragma unroll 8
        for (int kk = 0; kk < 32; kk++) {
            float x0 = sH[tr][k0 + kk], x1 = sH[tr + 16][k0 + kk];
#pragma unroll
            for (int c = 0; c < 8; c++) {
                float mv = sM[kk][tc + c * 16];
                acc[0][c] += x0 * mv;
                acc[1][c] += x1 * mv;
            }
        }
        __syncthreads();
    }
#pragma unroll
    for (int a = 0; a < 2; a++)
#pragma unroll
        for (int c = 0; c < 8; c++) {
            const int r = tr + a * 16, col = tc + c * 16;
            const float v = acc[a][c];
            const __nv_bfloat16 hi = __float2bfloat16_rn(v);
            const size_t o = (size_t)(row0 + r) * D + col;
            g_Gh[o] = hi;
            g_Gl[o] = __float2bfloat16_rn(v - __bfloat162float(hi));
        }

    const int nn = tid & 31, d0 = tid >> 5;
#pragma unroll
    for (int dp = 0; dp < 16; dp++) {
        const int d = dp * 8 + d0;
        g_hT[((size_t)b * D + d) * N + n0 + nn] = sH[nn][d];
    }
}

// ---------------------------------------------------------------------------
// Esym = G.h^T (K=128, 2 chunks), 512 threads, upper-triangle tile pairs.
__device__ __forceinline__ void esym_issue(int q, int stage, uint32_t sbase,
                                           size_t arow, size_t brow, int tid) {
    const int koff = q * 64;
    const uint32_t s = sbase + (uint32_t)stage * STAGE_B;
    issue_tile(s,              g_Gh, arow, D, koff, tid);
    issue_tile(s + TILE_B,     g_Gl, arow, D, koff, tid);
    issue_tile(s + 2 * TILE_B, g_hh, brow, D, koff, tid);
    issue_tile(s + 3 * TILE_B, g_hl, brow, D, koff, tid);
    CP_COMMIT();
}

__global__ void __launch_bounds__(NT) esym_k(const float* __restrict__ adj) {
    extern __shared__ char sm[];
    const uint32_t sbase = smem_u32(sm);
    const int tid = threadIdx.x, wid = tid >> 5, lane = tid & 31;
    const int wr = wid >> 2, wc = wid & 3;

    int t = blockIdx.x % 136;
    const int b = blockIdx.x / 136;
    int tj = 0;
    while (t >= 16 - tj) { t -= 16 - tj; tj++; }
    const int tk = tj + t;
    const int j0 = tj * 128, k0 = tk * 128;
    const size_t arow = (size_t)b * N + j0, brow = (size_t)b * N + k0;
    const float* adjb = adj + (size_t)b * N * N;

    float acc[2][4][4];
#pragma unroll
    for (int mi = 0; mi < 2; mi++)
#pragma unroll
        for (int ni = 0; ni < 4; ni++)
#pragma unroll
            for (int q = 0; q < 4; q++) acc[mi][ni][q] = 0.0f;

    esym_issue(0, 0, sbase, arow, brow, tid);
    esym_issue(1, 1, sbase, arow, brow, tid);
    adj_issue(sbase + 2 * STAGE_B, adjb, j0, k0, tid);

    CP_WAIT(2); __syncthreads();
    mma_tri(sbase, sbase + TILE_B, sbase + 2 * TILE_B, sbase + 3 * TILE_B,
            wr, wc, lane, acc);
    __syncthreads();
    if (tj != tk) {
        adj_issue(sbase, adjb, k0, j0, tid);
        CP_WAIT(2);
    } else {
        CP_WAIT(1);
    }
    __syncthreads();
    {
        const uint32_t s = sbase + STAGE_B;
        mma_tri(s, s + TILE_B, s + 2 * TILE_B, s + 3 * TILE_B, wr, wc, lane, acc);
    }
    CP_WAIT(0);
    __syncthreads();

    float* sD  = (float*)(sm + STAGE_B);
    float* sA1 = (float*)(sm + 2 * STAGE_B);
    float* sA2 = (float*)sm;
    acc_to_smem(sD, wr, wc, lane, acc, true);
    __syncthreads();

    const int c2 = (tid & 63) * 2;
    const int p = tid >> 6;                // 0..7
    {
        float cs0 = 0.0f, cs1 = 0.0f;
        const size_t ub = (size_t)b * N * N + (size_t)j0 * N + k0;
#pragma unroll 8
        for (int it = 0; it < 16; it++) {
            const int r = it * 8 + p;
            const float v0 = (sA1[r * ADJ_LDS + c2] > 0.0f) ? sD[r * 129 + c2] : 0.0f;
            const float v1 = (sA1[r * ADJ_LDS + c2 + 1] > 0.0f) ? sD[r * 129 + c2 + 1] : 0.0f;
            const float h0 = __bfloat162float(__float2bfloat16_rn(v0));
            const float h1 = __bfloat162float(__float2bfloat16_rn(v1));
            const size_t o2 = (ub + (size_t)r * N + c2) >> 1;
            ((uint32_t*)g_Uh)[o2] = pack_bf16(v0, v1);
            ((uint32_t*)g_Ul)[o2] = pack_bf16(v0 - h0, v1 - h1);
            cs0 += v0;
            cs1 += v1;
        }
        g_part[((size_t)b * N + k0 + c2) * 128 + tj * 8 + p] = cs0;
        g_part[((size_t)b * N + k0 + c2 + 1) * 128 + tj * 8 + p] = cs1;
    }
    if (tj != tk) {
        float cs0 = 0.0f, cs1 = 0.0f;
        const size_t ub = (size_t)b * N * N + (size_t)k0 * N + j0;
#pragma unroll 8
        for (int it = 0; it < 16; it++) {
            const int r = it * 8 + p;
            const float v0 = (sA2[r * ADJ_LDS + c2] > 0.0f) ? sD[c2 * 129 + r] : 0.0f;
            const float v1 = (sA2[r * ADJ_LDS + c2 + 1] > 0.0f) ? sD[(c2 + 1) * 129 + r] : 0.0f;
            const float h0 = __bfloat162float(__float2bfloat16_rn(v0));
            const float h1 = __bfloat162float(__float2bfloat16_rn(v1));
            const size_t o2 = (ub + (size_t)r * N + c2) >> 1;
            ((uint32_t*)g_Uh)[o2] = pack_bf16(v0, v1);
            ((uint32_t*)g_Ul)[o2] = pack_bf16(v0 - h0, v1 - h1);
            cs0 += v0;
            cs1 += v1;
        }
        g_part[((size_t)b * N + j0 + c2) * 128 + tk * 8 + p] = cs0;
        g_part[((size_t)b * N + j0 + c2 + 1) * 128 + tk * 8 + p] = cs1;
    }
}

// ---------------------------------------------------------------------------
// Per block: reduce is[] for 256 columns (128 slots each), scale 32 d-rows.
__global__ void __launch_bounds__(256) scale_is_k() {
    __shared__ float s_is[256];
    const int bx = blockIdx.x;
    const int b = bx >> 5;
    const int rem = bx & 31;
    const int j0 = (rem & 7) * 256;
    const int d0 = (rem >> 3) * 32;
    const int tid = threadIdx.x;

    {
        const float4* p = (const float4*)(g_part + ((size_t)b * N + j0 + tid) * 128);
        float s = 0.0f;
#pragma unroll
        for (int q = 0; q < 32; q++) {
            const float4 v = p[q];
            s += (v.x + v.y) + (v.z + v.w);
        }
        s_is[tid] = 1.0f / s;
    }
    __syncthreads();

    const int jq = tid & 63, dr0 = tid >> 6;
    const float4 sv = ((const float4*)s_is)[jq];
#pragma unroll
    for (int it = 0; it < 8; it++) {
        const int d = d0 + it * 4 + dr0;
        const size_t o4 = (((size_t)b * D + d) * N + j0) / 4 + jq;
        const float4 hv = ((const float4*)g_hT)[o4];
        const float v0 = hv.x * sv.x, v1 = hv.y * sv.y, v2 = hv.z * sv.z, v3 = hv.w * sv.w;
        const float h0 = __bfloat162float(__float2bfloat16_rn(v0));
        const float h1 = __bfloat162float(__float2bfloat16_rn(v1));
        const float h2 = __bfloat162float(__float2bfloat16_rn(v2));
        const float h3 = __bfloat162float(__float2bfloat16_rn(v3));
        uint2 ph, pl;
        ph.x = pack_bf16(v0, v1);
        ph.y = pack_bf16(v2, v3);
        pl.x = pack_bf16(v0 - h0, v1 - h1);
        pl.y = pack_bf16(v2 - h2, v3 - h3);
        ((uint2*)g_sh)[o4] = ph;
        ((uint2*)g_sl)[o4] = pl;
    }
}

// ---------------------------------------------------------------------------
// hp+gate fused: 512 threads, 32 chunks; depth-2 prefetch on 3 stages.
__device__ __forceinline__ void hp_issue(int c, int stage, uint32_t sbase,
                                         size_t arow, size_t brow, int tid) {
    const int koff = c * 64;
    const uint32_t s = sbase + (uint32_t)stage * STAGE_B;
    issue_tile(s,              g_Uh, arow, N, koff, tid);
    issue_tile(s + TILE_B,     g_Ul, arow, N, koff, tid);
    issue_tile(s + 2 * TILE_B, g_sh, brow, N, koff, tid);
    issue_tile(s + 3 * TILE_B, g_sl, brow, N, koff, tid);
    CP_COMMIT();
}

__global__ void __launch_bounds__(NT) hp_k(
    const float* __restrict__ x, const float* __restrict__ gw,
    const float* __restrict__ gb, float* __restrict__ out) {
    extern __shared__ char sm[];
    const uint32_t sbase = smem_u32(sm);
    const int tid = threadIdx.x, wid = tid >> 5, lane = tid & 31;
    const int wr = wid >> 2, wc = wid & 3;
    const int b = blockIdx.y;
    const int i0 = blockIdx.x * 128;
    const size_t arow = (size_t)b * N + i0;
    const size_t brow = (size_t)b * D;

    float acc[2][4][4];
#pragma unroll
    for (int mi = 0; mi < 2; mi++)
#pragma unroll
        for (int ni = 0; ni < 4; ni++)
#pragma unroll
            for (int q = 0; q < 4; q++) acc[mi][ni][q] = 0.0f;

    hp_issue(0, 0, sbase, arow, brow, tid);
    hp_issue(1, 1, sbase, arow, brow, tid);
#pragma unroll 1
    for (int c = 0; c < 32; c++) {
        if (c < 31) CP_WAIT(1);
        else CP_WAIT(0);
        __syncthreads();
        if (c + 2 < 32) hp_issue(c + 2, (c + 2) % 3, sbase, arow, brow, tid);
        const uint32_t s = sbase + (uint32_t)(c % 3) * STAGE_B;
        mma_tri(s, s + TILE_B, s + 2 * TILE_B, s + 3 * TILE_B, wr, wc, lane, acc);
    }
    __syncthreads();

    float* sD = (float*)sm;
    acc_to_smem(sD, wr, wc, lane, acc, false);
    __syncthreads();

    const float4 g1 = ((const float4*)gw)[lane];
    const float4 g2 = ((const float4*)(gw + D))[lane];
    const float gbv = gb[0];
#pragma unroll 1
    for (int rr = wid; rr < 128; rr += 16) {
        const size_t row = (size_t)b * N + i0 + rr;
        const float4 xv = ((const float4*)(x + row * D))[lane];
        float4 hv;
        hv.x = fmaxf(sD[rr * 129 + lane * 4 + 0], 0.0f);
        hv.y = fmaxf(sD[rr * 129 + lane * 4 + 1], 0.0f);
        hv.z = fmaxf(sD[rr * 129 + lane * 4 + 2], 0.0f);
        hv.w = fmaxf(sD[rr * 129 + lane * 4 + 3], 0.0f);
        float p = xv.x * g1.x + xv.y * g1.y + xv.z * g1.z + xv.w * g1.w
                + hv.x * g2.x + hv.y * g2.y + hv.z * g2.z + hv.w * g2.w;
#pragma unroll
        for (int o = 16; o > 0; o >>= 1) p += __shfl_xor_sync(0xffffffffu, p, o);
        const float cf = 1.0f / (1.0f + __expf(-(p + gbv)));
        const float df = 1.0f - cf;
        float4 o4;
        o4.x = cf * xv.x + df * hv.x;
        o4.y = cf * xv.y + df * hv.y;
        o4.z = cf * xv.z + df * hv.z;
        o4.w = cf * xv.w + df * hv.w;
        ((float4*)(out + row * D))[lane] = o4;
    }
}

// ---------------------------------------------------------------------------
extern "C" void kernel_launch(void* const* d_in, const int* in_sizes, int n_in,
                              void* d_out, int out_size) {
    const float* x   = (const float*)d_in[0];
    const float* adj = (const float*)d_in[1];
    const float* W_w = (const float*)d_in[2];
    const float* W_b = (const float*)d_in[3];
    const float* A   = (const float*)d_in[4];
    const float* gw  = (const float*)d_in[5];
    const float* gb  = (const float*)d_in[6];
    float* out = (float*)d_out;

    static bool attr_done = false;
    if (!attr_done) {
        cudaFuncSetAttribute(esym_k, cudaFuncAttributeMaxDynamicSharedMemorySize, SMEM_MMA);
        cudaFuncSetAttribute(hp_k,   cudaFuncAttributeMaxDynamicSharedMemorySize, SMEM_MMA);
        attr_done = true;
    }

    prep_wm_k<<<dim3(4, 4), dim3(32, 8)>>>(W_w, A);
    fused_h_k<<<(B * N) / 32, 256>>>(x, W_b);
    esym_k<<<B * 136, NT, SMEM_MMA>>>(adj);
    scale_is_k<<<B * 32, 256>>>();
    hp_k<<<dim3(N / 128, B), NT, SMEM_MMA>>>(x, gw, gb, out);
}

// round 15
// speedup vs baseline: 1.1238x; 1.0325x over previous
#include <cuda_runtime.h>
#include <cuda_bf16.h>
#include <cstdint>

namespace {
constexpr int B = 8;
constexpr int N = 2048;
constexpr int D = 128;
constexpr int LDS = 72;                    // padded smem row (bf16 elems)
constexpr int TILE_B = 128 * LDS * 2;      // 18432 bytes per operand tile
constexpr int STAGE_B = 4 * TILE_B;        // 73728: Ah, Al, Bh, Bl
constexpr int SMEM_MMA = 3 * STAGE_B;      // 221184
constexpr int ADJ_LDS = 132;               // fp32 elems per adj smem row
constexpr int NT = 512;                    // threads in MMA kernels
}

// ---------------------------------------------------------------------------
// Scratch (static device globals; no runtime allocation).
__device__ float g_Wt[D * D];
__device__ float g_M[D * D];               // A + A^T
__device__ float g_hT[B * D * N];
__device__ float g_part[(size_t)B * N * 16];
__device__ __nv_bfloat16 g_hh[B * N * D];
__device__ __nv_bfloat16 g_hl[B * N * D];
__device__ __nv_bfloat16 g_Gh[B * N * D];  // splits of G = h.(A+A^T)
__device__ __nv_bfloat16 g_Gl[B * N * D];
__device__ __nv_bfloat16 g_sh[B * D * N];
__device__ __nv_bfloat16 g_sl[B * D * N];
__device__ __nv_bfloat16 g_Uh[(size_t)B * N * N];
__device__ __nv_bfloat16 g_Ul[(size_t)B * N * N];

// ---------------------------------------------------------------------------
__device__ __forceinline__ uint32_t smem_u32(const void* p) {
    uint32_t a;
    asm("{ .reg .u64 t; cvta.to.shared.u64 t, %1; cvt.u32.u64 %0, t; }" : "=r"(a) : "l"(p));
    return a;
}
__device__ __forceinline__ void cp16(uint32_t dst, const void* src) {
    asm volatile("cp.async.cg.shared.global [%0], [%1], 16;" :: "r"(dst), "l"(src));
}
#define CP_COMMIT() asm volatile("cp.async.commit_group;" ::: "memory")
#define CP_WAIT(n)  asm volatile("cp.async.wait_group %0;" :: "n"(n) : "memory")

// 512-thread tile loader: 128x64 bf16 tile, 2 x 16B per thread.
__device__ __forceinline__ void issue_tile(uint32_t sdst,
                                           const __nv_bfloat16* __restrict__ base,
                                           size_t row0, int stride, int koff, int tid) {
#pragma unroll
    for (int t = 0; t < 2; t++) {
        const int i = t * NT + tid;
        const int rr = i >> 3, c16 = i & 7;
        cp16(sdst + (uint32_t)(rr * LDS + c16 * 8) * 2,
             base + (row0 + rr) * (size_t)stride + koff + c16 * 8);
    }
}

// 512-thread adj loader: 128x128 fp32 tile (row stride ADJ_LDS floats).
__device__ __forceinline__ void adj_issue(uint32_t sdst, const float* __restrict__ adjb,
                                          int r0, int c0, int tid) {
#pragma unroll
    for (int t = 0; t < 8; t++) {
        const int i = t * NT + tid;
        const int rr = i >> 5, cc = i & 31;
        cp16(sdst + (uint32_t)(rr * ADJ_LDS + cc * 4) * 4,
             adjb + (size_t)(r0 + rr) * N + c0 + cc * 4);
    }
    CP_COMMIT();
}

// ---------------------------------------------------------------------------
// Fragment loaders for the m16n8k16 layout. Warp tile 32(m) x 32(n).
__device__ __forceinline__ void lda_frag(uint32_t sA, int wr, int mi, int kk, int lane,
                                         uint32_t (&a)[4]) {
    const uint32_t addr = sA +
        ((wr * 32 + mi * 16 + (lane & 15)) * LDS + kk * 16 + ((lane >> 4) << 3)) * 2;
    asm volatile("ldmatrix.sync.aligned.m8n8.x4.shared.b16 {%0,%1,%2,%3}, [%4];"
                 : "=r"(a[0]), "=r"(a[1]), "=r"(a[2]), "=r"(a[3]) : "r"(addr));
}
__device__ __forceinline__ void ldb_frag4(uint32_t sB, int wc, int p, int kk, int lane,
                                          uint32_t (&b0)[2], uint32_t (&b1)[2]) {
    const uint32_t addr = sB +
        ((wc * 32 + (2 * p + ((lane >> 4) & 1)) * 8 + (lane & 7)) * LDS +
         kk * 16 + (((lane >> 3) & 1) << 3)) * 2;
    asm volatile("ldmatrix.sync.aligned.m8n8.x4.shared.b16 {%0,%1,%2,%3}, [%4];"
                 : "=r"(b0[0]), "=r"(b0[1]), "=r"(b1[0]), "=r"(b1[1]) : "r"(addr));
}
__device__ __forceinline__ void mma16816(float (&d)[4], const uint32_t (&a)[4],
                                         const uint32_t (&b)[2]) {
    asm volatile(
        "mma.sync.aligned.m16n8k16.row.col.f32.bf16.bf16.f32 "
        "{%0,%1,%2,%3}, {%4,%5,%6,%7}, {%8,%9}, {%0,%1,%2,%3};"
        : "+f"(d[0]), "+f"(d[1]), "+f"(d[2]), "+f"(d[3])
        : "r"(a[0]), "r"(a[1]), "r"(a[2]), "r"(a[3]), "r"(b[0]), "r"(b[1]));
}

// Three-term split MMA over one 64-wide K chunk; warp tile 32x32.
// Software-pipelined: lo operands of kk and hi operands of kk+1 are issued
// before kk's MMA batches, so ldmatrix latency overlaps tensor work.
// acc += Ah.Bh + Ah.Bl + Al.Bh
__device__ __forceinline__ void mma_tri(uint32_t sAh, uint32_t sAl,
                                        uint32_t sBh, uint32_t sBl,
                                        int wr, int wc, int lane,
                                        float (&acc)[2][4][4]) {
    uint32_t ah[2][4], bh[4][2], ahn[2][4], bhn[4][2];
#pragma unroll
    for (int mi = 0; mi < 2; mi++) lda_frag(sAh, wr, mi, 0, lane, ah[mi]);
#pragma unroll
    for (int p = 0; p < 2; p++) ldb_frag4(sBh, wc, p, 0, lane, bh[2 * p], bh[2 * p + 1]);
#pragma unroll
    for (int kk = 0; kk < 4; kk++) {
        uint32_t al[2][4], bl[4][2];
#pragma unroll
        for (int p = 0; p < 2; p++) ldb_frag4(sBl, wc, p, kk, lane, bl[2 * p], bl[2 * p + 1]);
#pragma unroll
        for (int mi = 0; mi < 2; mi++) lda_frag(sAl, wr, mi, kk, lane, al[mi]);
        if (kk < 3) {
#pragma unroll
            for (int mi = 0; mi < 2; mi++) lda_frag(sAh, wr, mi, kk + 1, lane, ahn[mi]);
#pragma unroll
            for (int p = 0; p < 2; p++)
                ldb_frag4(sBh, wc, p, kk + 1, lane, bhn[2 * p], bhn[2 * p + 1]);
        }
#pragma unroll
        for (int mi = 0; mi < 2; mi++)
#pragma unroll
            for (int ni = 0; ni < 4; ni++) mma16816(acc[mi][ni], ah[mi], bh[ni]);
#pragma unroll
        for (int mi = 0; mi < 2; mi++)
#pragma unroll
            for (int ni = 0; ni < 4; ni++) mma16816(acc[mi][ni], ah[mi], bl[ni]);
#pragma unroll
        for (int mi = 0; mi < 2; mi++)
#pragma unroll
            for (int ni = 0; ni < 4; ni++) mma16816(acc[mi][ni], al[mi], bh[ni]);
        if (kk < 3) {
#pragma unroll
            for (int mi = 0; mi < 2; mi++)
#pragma unroll
                for (int q = 0; q < 4; q++) ah[mi][q] = ahn[mi][q];
#pragma unroll
            for (int ni = 0; ni < 4; ni++) {
                bh[ni][0] = bhn[ni][0];
                bh[ni][1] = bhn[ni][1];
            }
        }
    }
}

__device__ __forceinline__ void acc_to_smem(float* sD, int wr, int wc, int lane,
                                            const float (&acc)[2][4][4], bool do_exp) {
#pragma unroll
    for (int mi = 0; mi < 2; mi++)
#pragma unroll
        for (int ni = 0; ni < 4; ni++) {
            const int row = wr * 32 + mi * 16 + (lane >> 2);
            const int col = wc * 32 + ni * 8 + (lane & 3) * 2;
            if (do_exp) {
                sD[row * 129 + col]           = __expf(acc[mi][ni][0]);
                sD[row * 129 + col + 1]       = __expf(acc[mi][ni][1]);
                sD[(row + 8) * 129 + col]     = __expf(acc[mi][ni][2]);
                sD[(row + 8) * 129 + col + 1] = __expf(acc[mi][ni][3]);
            } else {
                sD[row * 129 + col]           = acc[mi][ni][0];
                sD[row * 129 + col + 1]       = acc[mi][ni][1];
                sD[(row + 8) * 129 + col]     = acc[mi][ni][2];
                sD[(row + 8) * 129 + col + 1] = acc[mi][ni][3];
            }
        }
}

__device__ __forceinline__ uint32_t pack_bf16(float a, float b) {
    const __nv_bfloat16 ha = __float2bfloat16_rn(a);
    const __nv_bfloat16 hb = __float2bfloat16_rn(b);
    uint32_t r;
    asm("mov.b32 %0, {%1, %2};" : "=r"(r)
        : "h"(*(const uint16_t*)&ha), "h"(*(const uint16_t*)&hb));
    return r;
}

// ---------------------------------------------------------------------------
// Wt = W^T (tiny).
__global__ void prep_w_k(const float* __restrict__ W) {
    __shared__ float tw[32][33];
    const int x = blockIdx.x * 32 + threadIdx.x;
    const int y0 = blockIdx.y * 32;
    for (int i = threadIdx.y; i < 32; i += 8) tw[i][threadIdx.x] = W[(y0 + i) * D + x];
    __syncthreads();
    const int xo = blockIdx.y * 32 + threadIdx.x;
    const int yo0 = blockIdx.x * 32;
    for (int i = threadIdx.y; i < 32; i += 8) g_Wt[(yo0 + i) * D + xo] = tw[threadIdx.x][i];
}
// M = A + A^T (tiny).
__global__ void prep_m_k(const float* __restrict__ A) {
    __shared__ float ta[32][33];
    const int bx = blockIdx.x, by = blockIdx.y;
    const int x = bx * 32 + threadIdx.x;
    const int y0 = by * 32;
    for (int i = threadIdx.y; i < 32; i += 8)
        ta[i][threadIdx.x] = A[(bx * 32 + i) * D + by * 32 + threadIdx.x];
    __syncthreads();
    for (int i = threadIdx.y; i < 32; i += 8)
        g_M[(y0 + i) * D + x] = A[(y0 + i) * D + x] + ta[threadIdx.x][i];
}

// ---------------------------------------------------------------------------
// Fused front end: h = x.Wt + b; G = h.M; bf16 splits of both; hT fp32.
__global__ void __launch_bounds__(256) fused_h_k(const float* __restrict__ x,
                                                 const float* __restrict__ bias) {
    __shared__ float sM[32][D + 1];
    __shared__ float sX[32][33];
    __shared__ float sH[32][D + 1];
    const int row0 = blockIdx.x * 32;
    const int b = row0 >> 11;
    const int n0 = row0 & (N - 1);
    const int tid = threadIdx.x;
    const int tc = tid & 15, tr = tid >> 4;
    float acc[2][8];

#pragma unroll
    for (int a = 0; a < 2; a++)
#pragma unroll
        for (int c = 0; c < 8; c++) acc[a][c] = 0.0f;
    for (int k0 = 0; k0 < D; k0 += 32) {
#pragma unroll
        for (int i = tid; i < 32 * D; i += 256)
            sM[i >> 7][i & 127] = g_Wt[(k0 + (i >> 7)) * D + (i & 127)];
#pragma unroll
        for (int i = tid; i < 1024; i += 256)
            sX[i >> 5][i & 31] = x[(size_t)(row0 + (i >> 5)) * D + k0 + (i & 31)];
        __syncthreads();
#pragma unroll 8
        for (int kk = 0; kk < 32; kk++) {
            float x0 = sX[tr][kk], x1 = sX[tr + 16][kk];
#pragma unroll
            for (int c = 0; c < 8; c++) {
                float mv = sM[kk][tc + c * 16];
                acc[0][c] += x0 * mv;
                acc[1][c] += x1 * mv;
            }
        }
        __syncthreads();
    }
#pragma unroll
    for (int a = 0; a < 2; a++)
#pragma unroll
        for (int c = 0; c < 8; c++) {
            const int r = tr + a * 16, col = tc + c * 16;
            const float v = acc[a][c] + bias[col];
            sH[r][col] = v;
            const __nv_bfloat16 hi = __float2bfloat16_rn(v);
            const size_t o = (size_t)(row0 + r) * D + col;
            g_hh[o] = hi;
            g_hl[o] = __float2bfloat16_rn(v - __bfloat162float(hi));
        }
    __syncthreads();

#pragma unroll
    for (int a = 0; a < 2; a++)
#pragma unroll
        for (int c = 0; c < 8; c++) acc[a][c] = 0.0f;
    for (int k0 = 0; k0 < D; k0 += 32) {
#pragma unroll
        for (int i = tid; i < 32 * D; i += 256)
            sM[i >> 7][i & 127] = g_M[(k0 + (i >> 7)) * D + (i & 127)];
        __syncthreads();
#pragma unroll 8
        for (int kk = 0; kk < 32; kk++) {
            float x0 = sH[tr][k0 + kk], x1 = sH[tr + 16][k0 + kk];
#pragma unroll
            for (int c = 0; c < 8; c++) {
                float mv = sM[kk][tc + c * 16];
                acc[0][c] += x0 * mv;
                acc[1][c] += x1 * mv;
            }
        }
        __syncthreads();
    }
#pragma unroll
    for (int a = 0; a < 2; a++)
#pragma unroll
        for (int c = 0; c < 8; c++) {
            const int r = tr + a * 16, col = tc + c * 16;
            const float v = acc[a][c];
            const __nv_bfloat16 hi = __float2bfloat16_rn(v);
            const size_t o = (size_t)(row0 + r) * D + col;
            g_Gh[o] = hi;
            g_Gl[o] = __float2bfloat16_rn(v - __bfloat162float(hi));
        }

    const int nn = tid & 31, d0 = tid >> 5;
#pragma unroll
    for (int dp = 0; dp < 16; dp++) {
        const int d = dp * 8 + d0;
        g_hT[((size_t)b * D + d) * N + n0 + nn] = sH[nn][d];
    }
}

// ---------------------------------------------------------------------------
// Esym = G.h^T (K=128, 2 chunks), 512 threads, upper-triangle tile pairs.
// Column partials reduced in-CTA to one slot per (column, tile).
__device__ __forceinline__ void esym_issue(int q, int stage, uint32_t sbase,
                                           size_t arow, size_t brow, int tid) {
    const int koff = q * 64;
    const uint32_t s = sbase + (uint32_t)stage * STAGE_B;
    issue_tile(s,              g_Gh, arow, D, koff, tid);
    issue_tile(s + TILE_B,     g_Gl, arow, D, koff, tid);
    issue_tile(s + 2 * TILE_B, g_hh, brow, D, koff, tid);
    issue_tile(s + 3 * TILE_B, g_hl, brow, D, koff, tid);
    CP_COMMIT();
}

__global__ void __launch_bounds__(NT) esym_k(const float* __restrict__ adj) {
    extern __shared__ char sm[];
    const uint32_t sbase = smem_u32(sm);
    const int tid = threadIdx.x, wid = tid >> 5, lane = tid & 31;
    const int wr = wid >> 2, wc = wid & 3;

    int t = blockIdx.x % 136;
    const int b = blockIdx.x / 136;
    int tj = 0;
    while (t >= 16 - tj) { t -= 16 - tj; tj++; }
    const int tk = tj + t;
    const int j0 = tj * 128, k0 = tk * 128;
    const size_t arow = (size_t)b * N + j0, brow = (size_t)b * N + k0;
    const float* adjb = adj + (size_t)b * N * N;

    float acc[2][4][4];
#pragma unroll
    for (int mi = 0; mi < 2; mi++)
#pragma unroll
        for (int ni = 0; ni < 4; ni++)
#pragma unroll
            for (int q = 0; q < 4; q++) acc[mi][ni][q] = 0.0f;

    esym_issue(0, 0, sbase, arow, brow, tid);
    esym_issue(1, 1, sbase, arow, brow, tid);
    adj_issue(sbase + 2 * STAGE_B, adjb, j0, k0, tid);

    CP_WAIT(2); __syncthreads();
    mma_tri(sbase, sbase + TILE_B, sbase + 2 * TILE_B, sbase + 3 * TILE_B,
            wr, wc, lane, acc);
    __syncthreads();
    if (tj != tk) {
        adj_issue(sbase, adjb, k0, j0, tid);
        CP_WAIT(2);
    } else {
        CP_WAIT(1);
    }
    __syncthreads();
    {
        const uint32_t s = sbase + STAGE_B;
        mma_tri(s, s + TILE_B, s + 2 * TILE_B, s + 3 * TILE_B, wr, wc, lane, acc);
    }
    CP_WAIT(0);
    __syncthreads();

    float* sD  = (float*)(sm + STAGE_B);
    float* sA1 = (float*)(sm + 2 * STAGE_B);
    float* sA2 = (float*)sm;
    float* red = (float*)(sm + STAGE_B + 66048);   // 1024 floats in sD tail
    acc_to_smem(sD, wr, wc, lane, acc, true);
    __syncthreads();

    const int c2 = (tid & 63) * 2;
    const int p = tid >> 6;                // 0..7
    {
        float cs0 = 0.0f, cs1 = 0.0f;
        const size_t ub = (size_t)b * N * N + (size_t)j0 * N + k0;
#pragma unroll 8
        for (int it = 0; it < 16; it++) {
            const int r = it * 8 + p;
            const float v0 = (sA1[r * ADJ_LDS + c2] > 0.0f) ? sD[r * 129 + c2] : 0.0f;
            const float v1 = (sA1[r * ADJ_LDS + c2 + 1] > 0.0f) ? sD[r * 129 + c2 + 1] : 0.0f;
            const float h0 = __bfloat162float(__float2bfloat16_rn(v0));
            const float h1 = __bfloat162float(__float2bfloat16_rn(v1));
            const size_t o2 = (ub + (size_t)r * N + c2) >> 1;
            ((uint32_t*)g_Uh)[o2] = pack_bf16(v0, v1);
            ((uint32_t*)g_Ul)[o2] = pack_bf16(v0 - h0, v1 - h1);
            cs0 += v0;
            cs1 += v1;
        }
        red[c2 * 8 + p] = cs0;
        red[(c2 + 1) * 8 + p] = cs1;
    }
    __syncthreads();
    if (tid < 128) {
        float s = 0.0f;
#pragma unroll
        for (int q = 0; q < 8; q++) s += red[tid * 8 + q];
        g_part[((size_t)b * N + k0 + tid) * 16 + tj] = s;
    }
    if (tj != tk) {
        __syncthreads();
        float cs0 = 0.0f, cs1 = 0.0f;
        const size_t ub = (size_t)b * N * N + (size_t)k0 * N + j0;
#pragma unroll 8
        for (int it = 0; it < 16; it++) {
            const int r = it * 8 + p;
            const float v0 = (sA2[r * ADJ_LDS + c2] > 0.0f) ? sD[c2 * 129 + r] : 0.0f;
            const float v1 = (sA2[r * ADJ_LDS + c2 + 1] > 0.0f) ? sD[(c2 + 1) * 129 + r] : 0.0f;
            const float h0 = __bfloat162float(__float2bfloat16_rn(v0));
            const float h1 = __bfloat162float(__float2bfloat16_rn(v1));
            const size_t o2 = (ub + (size_t)r * N + c2) >> 1;
            ((uint32_t*)g_Uh)[o2] = pack_bf16(v0, v1);
            ((uint32_t*)g_Ul)[o2] = pack_bf16(v0 - h0, v1 - h1);
            cs0 += v0;
            cs1 += v1;
        }
        red[c2 * 8 + p] = cs0;
        red[(c2 + 1) * 8 + p] = cs1;
        __syncthreads();
        if (tid < 128) {
            float s = 0.0f;
#pragma unroll
            for (int q = 0; q < 8; q++) s += red[tid * 8 + q];
            g_part[((size_t)b * N + j0 + tid) * 16 + tk] = s;
        }
    }
}

// ---------------------------------------------------------------------------
// Per block: reduce is[] for 256 columns (16 slots each), scale 32 d-rows.
__global__ void __launch_bounds__(256) scale_is_k() {
    __shared__ float s_is[256];
    const int bx = blockIdx.x;
    const int b = bx >> 5;
    const int rem = bx & 31;
    const int j0 = (rem & 7) * 256;
    const int d0 = (rem >> 3) * 32;
    const int tid = threadIdx.x;

    {
        const float4* p = (const float4*)(g_part + ((size_t)b * N + j0 + tid) * 16);
        float s = 0.0f;
#pragma unroll
        for (int q = 0; q < 4; q++) {
            const float4 v = p[q];
            s += (v.x + v.y) + (v.z + v.w);
        }
        s_is[tid] = 1.0f / s;
    }
    __syncthreads();

    const int jq = tid & 63, dr0 = tid >> 6;
    const float4 sv = ((const float4*)s_is)[jq];
#pragma unroll
    for (int it = 0; it < 8; it++) {
        const int d = d0 + it * 4 + dr0;
        const size_t o4 = (((size_t)b * D + d) * N + j0) / 4 + jq;
        const float4 hv = ((const float4*)g_hT)[o4];
        const float v0 = hv.x * sv.x, v1 = hv.y * sv.y, v2 = hv.z * sv.z, v3 = hv.w * sv.w;
        const float h0 = __bfloat162float(__float2bfloat16_rn(v0));
        const float h1 = __bfloat162float(__float2bfloat16_rn(v1));
        const float h2 = __bfloat162float(__float2bfloat16_rn(v2));
        const float h3 = __bfloat162float(__float2bfloat16_rn(v3));
        uint2 ph, pl;
        ph.x = pack_bf16(v0, v1);
        ph.y = pack_bf16(v2, v3);
        pl.x = pack_bf16(v0 - h0, v1 - h1);
        pl.y = pack_bf16(v2 - h2, v3 - h3);
        ((uint2*)g_sh)[o4] = ph;
        ((uint2*)g_sl)[o4] = pl;
    }
}

// ---------------------------------------------------------------------------
// hp+gate fused: 512 threads, 32 chunks; depth-2 prefetch on 3 stages.
__device__ __forceinline__ void hp_issue(int c, int stage, uint32_t sbase,
                                         size_t arow, size_t brow, int tid) {
    const int koff = c * 64;
    const uint32_t s = sbase + (uint32_t)stage * STAGE_B;
    issue_tile(s,              g_Uh, arow, N, koff, tid);
    issue_tile(s + TILE_B,     g_Ul, arow, N, koff, tid);
    issue_tile(s + 2 * TILE_B, g_sh, brow, N, koff, tid);
    issue_tile(s + 3 * TILE_B, g_sl, brow, N, koff, tid);
    CP_COMMIT();
}

__global__ void __launch_bounds__(NT) hp_k(
    const float* __restrict__ x, const float* __restrict__ gw,
    const float* __restrict__ gb, float* __restrict__ out) {
    extern __shared__ char sm[];
    const uint32_t sbase = smem_u32(sm);
    const int tid = threadIdx.x, wid = tid >> 5, lane = tid & 31;
    const int wr = wid >> 2, wc = wid & 3;
    const int b = blockIdx.y;
    const int i0 = blockIdx.x * 128;
    const size_t arow = (size_t)b * N + i0;
    const size_t brow = (size_t)b * D;

    float acc[2][4][4];
#pragma unroll
    for (int mi = 0; mi < 2; mi++)
#pragma unroll
        for (int ni = 0; ni < 4; ni++)
#pragma unroll
            for (int q = 0; q < 4; q++) acc[mi][ni][q] = 0.0f;

    hp_issue(0, 0, sbase, arow, brow, tid);
    hp_issue(1, 1, sbase, arow, brow, tid);
#pragma unroll 1
    for (int c = 0; c < 32; c++) {
        if (c < 31) CP_WAIT(1);
        else CP_WAIT(0);
        __syncthreads();
        if (c + 2 < 32) hp_issue(c + 2, (c + 2) % 3, sbase, arow, brow, tid);
        const uint32_t s = sbase + (uint32_t)(c % 3) * STAGE_B;
        mma_tri(s, s + TILE_B, s + 2 * TILE_B, s + 3 * TILE_B, wr, wc, lane, acc);
    }
    __syncthreads();

    float* sD = (float*)sm;
    acc_to_smem(sD, wr, wc, lane, acc, false);
    __syncthreads();

    const float4 g1 = ((const float4*)gw)[lane];
    const float4 g2 = ((const float4*)(gw + D))[lane];
    const float gbv = gb[0];
#pragma unroll 1
    for (int rr = wid; rr < 128; rr += 16) {
        const size_t row = (size_t)b * N + i0 + rr;
        const float4 xv = ((const float4*)(x + row * D))[lane];
        float4 hv;
        hv.x = fmaxf(sD[rr * 129 + lane * 4 + 0], 0.0f);
        hv.y = fmaxf(sD[rr * 129 + lane * 4 + 1], 0.0f);
        hv.z = fmaxf(sD[rr * 129 + lane * 4 + 2], 0.0f);
        hv.w = fmaxf(sD[rr * 129 + lane * 4 + 3], 0.0f);
        float p = xv.x * g1.x + xv.y * g1.y + xv.z * g1.z + xv.w * g1.w
                + hv.x * g2.x + hv.y * g2.y + hv.z * g2.z + hv.w * g2.w;
#pragma unroll
        for (int o = 16; o > 0; o >>= 1) p += __shfl_xor_sync(0xffffffffu, p, o);
        const float cf = 1.0f / (1.0f + __expf(-(p + gbv)));
        const float df = 1.0f - cf;
        float4 o4;
        o4.x = cf * xv.x + df * hv.x;
        o4.y = cf * xv.y + df * hv.y;
        o4.z = cf * xv.z + df * hv.z;
        o4.w = cf * xv.w + df * hv.w;
        ((float4*)(out + row * D))[lane] = o4;
    }
}

// ---------------------------------------------------------------------------
extern "C" void kernel_launch(void* const* d_in, const int* in_sizes, int n_in,
                              void* d_out, int out_size) {
    const float* x   = (const float*)d_in[0];
    const float* adj = (const float*)d_in[1];
    const float* W_w = (const float*)d_in[2];
    const float* W_b = (const float*)d_in[3];
    const float* A   = (const float*)d_in[4];
    const float* gw  = (const float*)d_in[5];
    const float* gb  = (const float*)d_in[6];
    float* out = (float*)d_out;

    static bool attr_done = false;
    if (!attr_done) {
        cudaFuncSetAttribute(esym_k, cudaFuncAttributeMaxDynamicSharedMemorySize, SMEM_MMA);
        cudaFuncSetAttribute(hp_k,   cudaFuncAttributeMaxDynamicSharedMemorySize, SMEM_MMA);
        attr_done = true;
    }

    prep_w_k<<<dim3(4, 4), dim3(32, 8)>>>(W_w);
    prep_m_k<<<dim3(4, 4), dim3(32, 8)>>>(A);
    fused_h_k<<<(B * N) / 32, 256>>>(x, W_b);
    esym_k<<<B * 136, NT, SMEM_MMA>>>(adj);     // 4th launch -> profiled next round
    scale_is_k<<<B * 32, 256>>>();
    hp_k<<<dim3(N / 128, B), NT, SMEM_MMA>>>(x, gw, gb, out);
}

// round 16
// speedup vs baseline: 1.2724x; 1.1323x over previous
#include <cuda_runtime.h>
#include <cuda_bf16.h>
#include <cstdint>

namespace {
constexpr int B = 8;
constexpr int N = 2048;
constexpr int D = 128;
constexpr int LDS = 72;                    // padded smem row (bf16 elems)
constexpr int TILE_B = 128 * LDS * 2;      // 18432 bytes per operand tile
constexpr int STAGE_B = 4 * TILE_B;        // esym stage: Gh, Gl, hh, hl
constexpr int SMEM_ESY = 3 * STAGE_B;      // 221184
constexpr int STAGE_HP = 3 * TILE_B;       // hp stage: Uh, sh, sl
constexpr int SMEM_HP  = 4 * STAGE_HP;     // 221184 (4-stage)
constexpr int ADJ_LDS = 132;               // fp32 elems per adj smem row
constexpr int NT = 512;                    // threads in MMA kernels
}

// ---------------------------------------------------------------------------
// Scratch (static device globals; no runtime allocation).
__device__ float g_Wt[D * D];
__device__ float g_M[D * D];               // A + A^T
__device__ float g_hT[B * D * N];
__device__ float g_part[(size_t)B * N * 16];
__device__ __nv_bfloat16 g_hh[B * N * D];
__device__ __nv_bfloat16 g_hl[B * N * D];
__device__ __nv_bfloat16 g_Gh[B * N * D];  // splits of G = h.(A+A^T)
__device__ __nv_bfloat16 g_Gl[B * N * D];
__device__ __nv_bfloat16 g_sh[B * D * N];  // splits of is[j]*h^T
__device__ __nv_bfloat16 g_sl[B * D * N];
__device__ __nv_bfloat16 g_Uh[(size_t)B * N * N];  // bf16(masked exp(e_sym))

// ---------------------------------------------------------------------------
__device__ __forceinline__ uint32_t smem_u32(const void* p) {
    uint32_t a;
    asm("{ .reg .u64 t; cvta.to.shared.u64 t, %1; cvt.u32.u64 %0, t; }" : "=r"(a) : "l"(p));
    return a;
}
__device__ __forceinline__ void cp16(uint32_t dst, const void* src) {
    asm volatile("cp.async.cg.shared.global [%0], [%1], 16;" :: "r"(dst), "l"(src));
}
#define CP_COMMIT() asm volatile("cp.async.commit_group;" ::: "memory")
#define CP_WAIT(n)  asm volatile("cp.async.wait_group %0;" :: "n"(n) : "memory")

// 512-thread tile loader: 128x64 bf16 tile, 2 x 16B per thread.
__device__ __forceinline__ void issue_tile(uint32_t sdst,
                                           const __nv_bfloat16* __restrict__ base,
                                           size_t row0, int stride, int koff, int tid) {
#pragma unroll
    for (int t = 0; t < 2; t++) {
        const int i = t * NT + tid;
        const int rr = i >> 3, c16 = i & 7;
        cp16(sdst + (uint32_t)(rr * LDS + c16 * 8) * 2,
             base + (row0 + rr) * (size_t)stride + koff + c16 * 8);
    }
}

// 512-thread adj loader: 128x128 fp32 tile (row stride ADJ_LDS floats).
__device__ __forceinline__ void adj_issue(uint32_t sdst, const float* __restrict__ adjb,
                                          int r0, int c0, int tid) {
#pragma unroll
    for (int t = 0; t < 8; t++) {
        const int i = t * NT + tid;
        const int rr = i >> 5, cc = i & 31;
        cp16(sdst + (uint32_t)(rr * ADJ_LDS + cc * 4) * 4,
             adjb + (size_t)(r0 + rr) * N + c0 + cc * 4);
    }
    CP_COMMIT();
}

// ---------------------------------------------------------------------------
// Fragment loaders for the m16n8k16 layout. Warp tile 32(m) x 32(n).
__device__ __forceinline__ void lda_frag(uint32_t sA, int wr, int mi, int kk, int lane,
                                         uint32_t (&a)[4]) {
    const uint32_t addr = sA +
        ((wr * 32 + mi * 16 + (lane & 15)) * LDS + kk * 16 + ((lane >> 4) << 3)) * 2;
    asm volatile("ldmatrix.sync.aligned.m8n8.x4.shared.b16 {%0,%1,%2,%3}, [%4];"
                 : "=r"(a[0]), "=r"(a[1]), "=r"(a[2]), "=r"(a[3]) : "r"(addr));
}
__device__ __forceinline__ void ldb_frag4(uint32_t sB, int wc, int p, int kk, int lane,
                                          uint32_t (&b0)[2], uint32_t (&b1)[2]) {
    const uint32_t addr = sB +
        ((wc * 32 + (2 * p + ((lane >> 4) & 1)) * 8 + (lane & 7)) * LDS +
         kk * 16 + (((lane >> 3) & 1) << 3)) * 2;
    asm volatile("ldmatrix.sync.aligned.m8n8.x4.shared.b16 {%0,%1,%2,%3}, [%4];"
                 : "=r"(b0[0]), "=r"(b0[1]), "=r"(b1[0]), "=r"(b1[1]) : "r"(addr));
}
__device__ __forceinline__ void mma16816(float (&d)[4], const uint32_t (&a)[4],
                                         const uint32_t (&b)[2]) {
    asm volatile(
        "mma.sync.aligned.m16n8k16.row.col.f32.bf16.bf16.f32 "
        "{%0,%1,%2,%3}, {%4,%5,%6,%7}, {%8,%9}, {%0,%1,%2,%3};"
        : "+f"(d[0]), "+f"(d[1]), "+f"(d[2]), "+f"(d[3])
        : "r"(a[0]), "r"(a[1]), "r"(a[2]), "r"(a[3]), "r"(b[0]), "r"(b[1]));
}

// Three-term split MMA (esym): acc += Ah.Bh + Ah.Bl + Al.Bh, software-pipelined.
__device__ __forceinline__ void mma_tri(uint32_t sAh, uint32_t sAl,
                                        uint32_t sBh, uint32_t sBl,
                                        int wr, int wc, int lane,
                                        float (&acc)[2][4][4]) {
    uint32_t ah[2][4], bh[4][2], ahn[2][4], bhn[4][2];
#pragma unroll
    for (int mi = 0; mi < 2; mi++) lda_frag(sAh, wr, mi, 0, lane, ah[mi]);
#pragma unroll
    for (int p = 0; p < 2; p++) ldb_frag4(sBh, wc, p, 0, lane, bh[2 * p], bh[2 * p + 1]);
#pragma unroll
    for (int kk = 0; kk < 4; kk++) {
        uint32_t al[2][4], bl[4][2];
#pragma unroll
        for (int p = 0; p < 2; p++) ldb_frag4(sBl, wc, p, kk, lane, bl[2 * p], bl[2 * p + 1]);
#pragma unroll
        for (int mi = 0; mi < 2; mi++) lda_frag(sAl, wr, mi, kk, lane, al[mi]);
        if (kk < 3) {
#pragma unroll
            for (int mi = 0; mi < 2; mi++) lda_frag(sAh, wr, mi, kk + 1, lane, ahn[mi]);
#pragma unroll
            for (int p = 0; p < 2; p++)
                ldb_frag4(sBh, wc, p, kk + 1, lane, bhn[2 * p], bhn[2 * p + 1]);
        }
#pragma unroll
        for (int mi = 0; mi < 2; mi++)
#pragma unroll
            for (int ni = 0; ni < 4; ni++) mma16816(acc[mi][ni], ah[mi], bh[ni]);
#pragma unroll
        for (int mi = 0; mi < 2; mi++)
#pragma unroll
            for (int ni = 0; ni < 4; ni++) mma16816(acc[mi][ni], ah[mi], bl[ni]);
#pragma unroll
        for (int mi = 0; mi < 2; mi++)
#pragma unroll
            for (int ni = 0; ni < 4; ni++) mma16816(acc[mi][ni], al[mi], bh[ni]);
        if (kk < 3) {
#pragma unroll
            for (int mi = 0; mi < 2; mi++)
#pragma unroll
                for (int q = 0; q < 4; q++) ah[mi][q] = ahn[mi][q];
#pragma unroll
            for (int ni = 0; ni < 4; ni++) {
                bh[ni][0] = bhn[ni][0];
                bh[ni][1] = bhn[ni][1];
            }
        }
    }
}

// Two-term split MMA (hp): acc += A.Bh + A.Bl, software-pipelined.
__device__ __forceinline__ void mma_duo(uint32_t sA, uint32_t sBh, uint32_t sBl,
                                        int wr, int wc, int lane,
                                        float (&acc)[2][4][4]) {
    uint32_t a[2][4], bh[4][2], an[2][4], bhn[4][2];
#pragma unroll
    for (int mi = 0; mi < 2; mi++) lda_frag(sA, wr, mi, 0, lane, a[mi]);
#pragma unroll
    for (int p = 0; p < 2; p++) ldb_frag4(sBh, wc, p, 0, lane, bh[2 * p], bh[2 * p + 1]);
#pragma unroll
    for (int kk = 0; kk < 4; kk++) {
        uint32_t bl[4][2];
#pragma unroll
        for (int p = 0; p < 2; p++) ldb_frag4(sBl, wc, p, kk, lane, bl[2 * p], bl[2 * p + 1]);
        if (kk < 3) {
#pragma unroll
            for (int mi = 0; mi < 2; mi++) lda_frag(sA, wr, mi, kk + 1, lane, an[mi]);
#pragma unroll
            for (int p = 0; p < 2; p++)
                ldb_frag4(sBh, wc, p, kk + 1, lane, bhn[2 * p], bhn[2 * p + 1]);
        }
#pragma unroll
        for (int mi = 0; mi < 2; mi++)
#pragma unroll
            for (int ni = 0; ni < 4; ni++) mma16816(acc[mi][ni], a[mi], bh[ni]);
#pragma unroll
        for (int mi = 0; mi < 2; mi++)
#pragma unroll
            for (int ni = 0; ni < 4; ni++) mma16816(acc[mi][ni], a[mi], bl[ni]);
        if (kk < 3) {
#pragma unroll
            for (int mi = 0; mi < 2; mi++)
#pragma unroll
                for (int q = 0; q < 4; q++) a[mi][q] = an[mi][q];
#pragma unroll
            for (int ni = 0; ni < 4; ni++) {
                bh[ni][0] = bhn[ni][0];
                bh[ni][1] = bhn[ni][1];
            }
        }
    }
}

__device__ __forceinline__ void acc_to_smem(float* sD, int wr, int wc, int lane,
                                            const float (&acc)[2][4][4], bool do_exp) {
#pragma unroll
    for (int mi = 0; mi < 2; mi++)
#pragma unroll
        for (int ni = 0; ni < 4; ni++) {
            const int row = wr * 32 + mi * 16 + (lane >> 2);
            const int col = wc * 32 + ni * 8 + (lane & 3) * 2;
            if (do_exp) {
                sD[row * 129 + col]           = __expf(acc[mi][ni][0]);
                sD[row * 129 + col + 1]       = __expf(acc[mi][ni][1]);
                sD[(row + 8) * 129 + col]     = __expf(acc[mi][ni][2]);
                sD[(row + 8) * 129 + col + 1] = __expf(acc[mi][ni][3]);
            } else {
                sD[row * 129 + col]           = acc[mi][ni][0];
                sD[row * 129 + col + 1]       = acc[mi][ni][1];
                sD[(row + 8) * 129 + col]     = acc[mi][ni][2];
                sD[(row + 8) * 129 + col + 1] = acc[mi][ni][3];
            }
        }
}

__device__ __forceinline__ uint32_t pack_bf16(float a, float b) {
    const __nv_bfloat16 ha = __float2bfloat16_rn(a);
    const __nv_bfloat16 hb = __float2bfloat16_rn(b);
    uint32_t r;
    asm("mov.b32 %0, {%1, %2};" : "=r"(r)
        : "h"(*(const uint16_t*)&ha), "h"(*(const uint16_t*)&hb));
    return r;
}

// ---------------------------------------------------------------------------
__global__ void prep_w_k(const float* __restrict__ W) {
    __shared__ float tw[32][33];
    const int x = blockIdx.x * 32 + threadIdx.x;
    const int y0 = blockIdx.y * 32;
    for (int i = threadIdx.y; i < 32; i += 8) tw[i][threadIdx.x] = W[(y0 + i) * D + x];
    __syncthreads();
    const int xo = blockIdx.y * 32 + threadIdx.x;
    const int yo0 = blockIdx.x * 32;
    for (int i = threadIdx.y; i < 32; i += 8) g_Wt[(yo0 + i) * D + xo] = tw[threadIdx.x][i];
}
__global__ void prep_m_k(const float* __restrict__ A) {
    __shared__ float ta[32][33];
    const int bx = blockIdx.x, by = blockIdx.y;
    const int x = bx * 32 + threadIdx.x;
    const int y0 = by * 32;
    for (int i = threadIdx.y; i < 32; i += 8)
        ta[i][threadIdx.x] = A[(bx * 32 + i) * D + by * 32 + threadIdx.x];
    __syncthreads();
    for (int i = threadIdx.y; i < 32; i += 8)
        g_M[(y0 + i) * D + x] = A[(y0 + i) * D + x] + ta[threadIdx.x][i];
}

// ---------------------------------------------------------------------------
// Fused front end: h = x.Wt + b; G = h.M; bf16 splits of both; hT fp32.
__global__ void __launch_bounds__(256) fused_h_k(const float* __restrict__ x,
                                                 const float* __restrict__ bias) {
    __shared__ float sM[32][D + 1];
    __shared__ float sX[32][33];
    __shared__ float sH[32][D + 1];
    const int row0 = blockIdx.x * 32;
    const int b = row0 >> 11;
    const int n0 = row0 & (N - 1);
    const int tid = threadIdx.x;
    const int tc = tid & 15, tr = tid >> 4;
    float acc[2][8];

#pragma unroll
    for (int a = 0; a < 2; a++)
#pragma unroll
        for (int c = 0; c < 8; c++) acc[a][c] = 0.0f;
    for (int k0 = 0; k0 < D; k0 += 32) {
#pragma unroll
        for (int i = tid; i < 32 * D; i += 256)
            sM[i >> 7][i & 127] = g_Wt[(k0 + (i >> 7)) * D + (i & 127)];
#pragma unroll
        for (int i = tid; i < 1024; i += 256)
            sX[i >> 5][i & 31] = x[(size_t)(row0 + (i >> 5)) * D + k0 + (i & 31)];
        __syncthreads();
#pragma unroll 8
        for (int kk = 0; kk < 32; kk++) {
            float x0 = sX[tr][kk], x1 = sX[tr + 16][kk];
#pragma unroll
            for (int c = 0; c < 8; c++) {
                float mv = sM[kk][tc + c * 16];
                acc[0][c] += x0 * mv;
                acc[1][c] += x1 * mv;
            }
        }
        __syncthreads();
    }
#pragma unroll
    for (int a = 0; a < 2; a++)
#pragma unroll
        for (int c = 0; c < 8; c++) {
            const int r = tr + a * 16, col = tc + c * 16;
            const float v = acc[a][c] + bias[col];
            sH[r][col] = v;
            const __nv_bfloat16 hi = __float2bfloat16_rn(v);
            const size_t o = (size_t)(row0 + r) * D + col;
            g_hh[o] = hi;
            g_hl[o] = __float2bfloat16_rn(v - __bfloat162float(hi));
        }
    __syncthreads();

#pragma unroll
    for (int a = 0; a < 2; a++)
#pragma unroll
        for (int c = 0; c < 8; c++) acc[a][c] = 0.0f;
    for (int k0 = 0; k0 < D; k0 += 32) {
#pragma unroll
        for (int i = tid; i < 32 * D; i += 256)
            sM[i >> 7][i & 127] = g_M[(k0 + (i >> 7)) * D + (i & 127)];
        __syncthreads();
#pragma unroll 8
        for (int kk = 0; kk < 32; kk++) {
            float x0 = sH[tr][k0 + kk], x1 = sH[tr + 16][k0 + kk];
#pragma unroll
            for (int c = 0; c < 8; c++) {
                float mv = sM[kk][tc + c * 16];
                acc[0][c] += x0 * mv;
                acc[1][c] += x1 * mv;
            }
        }
        __syncthreads();
    }
#pragma unroll
    for (int a = 0; a < 2; a++)
#pragma unroll
        for (int c = 0; c < 8; c++) {
            const int r = tr + a * 16, col = tc + c * 16;
            const float v = acc[a][c];
            const __nv_bfloat16 hi = __float2bfloat16_rn(v);
            const size_t o = (size_t)(row0 + r) * D + col;
            g_Gh[o] = hi;
            g_Gl[o] = __float2bfloat16_rn(v - __bfloat162float(hi));
        }

    const int nn = tid & 31, d0 = tid >> 5;
#pragma unroll
    for (int dp = 0; dp < 16; dp++) {
        const int d = dp * 8 + d0;
        g_hT[((size_t)b * D + d) * N + n0 + nn] = sH[nn][d];
    }
}

// ---------------------------------------------------------------------------
// Esym = G.h^T (K=128, 2 chunks), 512 threads, upper-triangle tile pairs.
// U stored bf16-only; interleaved orientation epilogue, one sync.
__device__ __forceinline__ void esym_issue(int q, int stage, uint32_t sbase,
                                           size_t arow, size_t brow, int tid) {
    const int koff = q * 64;
    const uint32_t s = sbase + (uint32_t)stage * STAGE_B;
    issue_tile(s,              g_Gh, arow, D, koff, tid);
    issue_tile(s + TILE_B,     g_Gl, arow, D, koff, tid);
    issue_tile(s + 2 * TILE_B, g_hh, brow, D, koff, tid);
    issue_tile(s + 3 * TILE_B, g_hl, brow, D, koff, tid);
    CP_COMMIT();
}

__global__ void __launch_bounds__(NT) esym_k(const float* __restrict__ adj) {
    extern __shared__ char sm[];
    const uint32_t sbase = smem_u32(sm);
    const int tid = threadIdx.x, wid = tid >> 5, lane = tid & 31;
    const int wr = wid >> 2, wc = wid & 3;

    int t = blockIdx.x % 136;
    const int b = blockIdx.x / 136;
    int tj = 0;
    while (t >= 16 - tj) { t -= 16 - tj; tj++; }
    const int tk = tj + t;
    const int j0 = tj * 128, k0 = tk * 128;
    const size_t arow = (size_t)b * N + j0, brow = (size_t)b * N + k0;
    const float* adjb = adj + (size_t)b * N * N;

    float acc[2][4][4];
#pragma unroll
    for (int mi = 0; mi < 2; mi++)
#pragma unroll
        for (int ni = 0; ni < 4; ni++)
#pragma unroll
            for (int q = 0; q < 4; q++) acc[mi][ni][q] = 0.0f;

    esym_issue(0, 0, sbase, arow, brow, tid);
    esym_issue(1, 1, sbase, arow, brow, tid);
    adj_issue(sbase + 2 * STAGE_B, adjb, j0, k0, tid);

    CP_WAIT(2); __syncthreads();
    mma_tri(sbase, sbase + TILE_B, sbase + 2 * TILE_B, sbase + 3 * TILE_B,
            wr, wc, lane, acc);
    __syncthreads();
    if (tj != tk) {
        adj_issue(sbase, adjb, k0, j0, tid);
        CP_WAIT(2);
    } else {
        CP_WAIT(1);
    }
    __syncthreads();
    {
        const uint32_t s = sbase + STAGE_B;
        mma_tri(s, s + TILE_B, s + 2 * TILE_B, s + 3 * TILE_B, wr, wc, lane, acc);
    }
    CP_WAIT(0);
    __syncthreads();

    float* sD   = (float*)(sm + STAGE_B);              // 66048 B in st1
    float* sA1  = (float*)(sm + 2 * STAGE_B);          // adj1, stride 132
    float* sA2  = (float*)sm;                          // adj2 (st0)
    float* red1 = (float*)(sm + 67584);                // st0 tail (4 KB)
    float* red2 = (float*)(sm + STAGE_B + 66048);      // st1 tail (4 KB)
    acc_to_smem(sD, wr, wc, lane, acc, true);
    __syncthreads();

    const int c2 = (tid & 63) * 2;
    const int p = tid >> 6;                // 0..7
    {
        float cs0 = 0.0f, cs1 = 0.0f;
        const size_t ub = (size_t)b * N * N + (size_t)j0 * N + k0;
#pragma unroll 8
        for (int it = 0; it < 16; it++) {
            const int r = it * 8 + p;
            const float v0 = (sA1[r * ADJ_LDS + c2] > 0.0f) ? sD[r * 129 + c2] : 0.0f;
            const float v1 = (sA1[r * ADJ_LDS + c2 + 1] > 0.0f) ? sD[r * 129 + c2 + 1] : 0.0f;
            ((uint32_t*)g_Uh)[(ub + (size_t)r * N + c2) >> 1] = pack_bf16(v0, v1);
            cs0 += v0;
            cs1 += v1;
        }
        red1[c2 * 8 + p] = cs0;
        red1[(c2 + 1) * 8 + p] = cs1;
    }
    if (tj != tk) {
        float cs0 = 0.0f, cs1 = 0.0f;
        const size_t ub = (size_t)b * N * N + (size_t)k0 * N + j0;
#pragma unroll 8
        for (int it = 0; it < 16; it++) {
            const int r = it * 8 + p;
            const float v0 = (sA2[r * ADJ_LDS + c2] > 0.0f) ? sD[c2 * 129 + r] : 0.0f;
            const float v1 = (sA2[r * ADJ_LDS + c2 + 1] > 0.0f) ? sD[(c2 + 1) * 129 + r] : 0.0f;
            ((uint32_t*)g_Uh)[(ub + (size_t)r * N + c2) >> 1] = pack_bf16(v0, v1);
            cs0 += v0;
            cs1 += v1;
        }
        red2[c2 * 8 + p] = cs0;
        red2[(c2 + 1) * 8 + p] = cs1;
    }
    __syncthreads();
    if (tid < 128) {
        float s = 0.0f;
#pragma unroll
        for (int q = 0; q < 8; q++) s += red1[tid * 8 + q];
        g_part[((size_t)b * N + k0 + tid) * 16 + tj] = s;
    } else if (tid < 256 && tj != tk) {
        const int cc = tid - 128;
        float s = 0.0f;
#pragma unroll
        for (int q = 0; q < 8; q++) s += red2[cc * 8 + q];
        g_part[((size_t)b * N + j0 + cc) * 16 + tk] = s;
    }
}

// ---------------------------------------------------------------------------
// Per block: reduce is[] for 256 columns (16 slots each), scale 32 d-rows.
__global__ void __launch_bounds__(256) scale_is_k() {
    __shared__ float s_is[256];
    const int bx = blockIdx.x;
    const int b = bx >> 5;
    const int rem = bx & 31;
    const int j0 = (rem & 7) * 256;
    const int d0 = (rem >> 3) * 32;
    const int tid = threadIdx.x;

    {
        const float4* p = (const float4*)(g_part + ((size_t)b * N + j0 + tid) * 16);
        float s = 0.0f;
#pragma unroll
        for (int q = 0; q < 4; q++) {
            const float4 v = p[q];
            s += (v.x + v.y) + (v.z + v.w);
        }
        s_is[tid] = 1.0f / s;
    }
    __syncthreads();

    const int jq = tid & 63, dr0 = tid >> 6;
    const float4 sv = ((const float4*)s_is)[jq];
#pragma unroll
    for (int it = 0; it < 8; it++) {
        const int d = d0 + it * 4 + dr0;
        const size_t o4 = (((size_t)b * D + d) * N + j0) / 4 + jq;
        const float4 hv = ((const float4*)g_hT)[o4];
        const float v0 = hv.x * sv.x, v1 = hv.y * sv.y, v2 = hv.z * sv.z, v3 = hv.w * sv.w;
        const float h0 = __bfloat162float(__float2bfloat16_rn(v0));
        const float h1 = __bfloat162float(__float2bfloat16_rn(v1));
        const float h2 = __bfloat162float(__float2bfloat16_rn(v2));
        const float h3 = __bfloat162float(__float2bfloat16_rn(v3));
        uint2 ph, pl;
        ph.x = pack_bf16(v0, v1);
        ph.y = pack_bf16(v2, v3);
        pl.x = pack_bf16(v0 - h0, v1 - h1);
        pl.y = pack_bf16(v2 - h2, v3 - h3);
        ((uint2*)g_sh)[o4] = ph;
        ((uint2*)g_sl)[o4] = pl;
    }
}

// ---------------------------------------------------------------------------
// hp+gate fused: 2-term (Uh.sh + Uh.sl), 4 stages, depth-3 prefetch.
__device__ __forceinline__ void hp_issue(int c, int stage, uint32_t sbase,
                                         size_t arow, size_t brow, int tid) {
    const int koff = c * 64;
    const uint32_t s = sbase + (uint32_t)stage * STAGE_HP;
    issue_tile(s,              g_Uh, arow, N, koff, tid);
    issue_tile(s + TILE_B,     g_sh, brow, N, koff, tid);
    issue_tile(s + 2 * TILE_B, g_sl, brow, N, koff, tid);
    CP_COMMIT();
}

__global__ void __launch_bounds__(NT) hp_k(
    const float* __restrict__ x, const float* __restrict__ gw,
    const float* __restrict__ gb, float* __restrict__ out) {
    extern __shared__ char sm[];
    const uint32_t sbase = smem_u32(sm);
    const int tid = threadIdx.x, wid = tid >> 5, lane = tid & 31;
    const int wr = wid >> 2, wc = wid & 3;
    const int b = blockIdx.y;
    const int i0 = blockIdx.x * 128;
    const size_t arow = (size_t)b * N + i0;
    const size_t brow = (size_t)b * D;

    float acc[2][4][4];
#pragma unroll
    for (int mi = 0; mi < 2; mi++)
#pragma unroll
        for (int ni = 0; ni < 4; ni++)
#pragma unroll
            for (int q = 0; q < 4; q++) acc[mi][ni][q] = 0.0f;

    hp_issue(0, 0, sbase, arow, brow, tid);
    hp_issue(1, 1, sbase, arow, brow, tid);
    hp_issue(2, 2, sbase, arow, brow, tid);
#pragma unroll 1
    for (int c = 0; c < 32; c++) {
        if (c < 30) CP_WAIT(2);
        else if (c == 30) CP_WAIT(1);
        else CP_WAIT(0);
        __syncthreads();
        if (c + 3 < 32) hp_issue(c + 3, (c + 3) & 3, sbase, arow, brow, tid);
        const uint32_t s = sbase + (uint32_t)(c & 3) * STAGE_HP;
        mma_duo(s, s + TILE_B, s + 2 * TILE_B, wr, wc, lane, acc);
    }
    __syncthreads();

    float* sD = (float*)sm;
    acc_to_smem(sD, wr, wc, lane, acc, false);
    __syncthreads();

    const float4 g1 = ((const float4*)gw)[lane];
    const float4 g2 = ((const float4*)(gw + D))[lane];
    const float gbv = gb[0];
#pragma unroll 1
    for (int rr = wid; rr < 128; rr += 16) {
        const size_t row = (size_t)b * N + i0 + rr;
        const float4 xv = ((const float4*)(x + row * D))[lane];
        float4 hv;
        hv.x = fmaxf(sD[rr * 129 + lane * 4 + 0], 0.0f);
        hv.y = fmaxf(sD[rr * 129 + lane * 4 + 1], 0.0f);
        hv.z = fmaxf(sD[rr * 129 + lane * 4 + 2], 0.0f);
        hv.w = fmaxf(sD[rr * 129 + lane * 4 + 3], 0.0f);
        float p = xv.x * g1.x + xv.y * g1.y + xv.z * g1.z + xv.w * g1.w
                + hv.x * g2.x + hv.y * g2.y + hv.z * g2.z + hv.w * g2.w;
#pragma unroll
        for (int o = 16; o > 0; o >>= 1) p += __shfl_xor_sync(0xffffffffu, p, o);
        const float cf = 1.0f / (1.0f + __expf(-(p + gbv)));
        const float df = 1.0f - cf;
        float4 o4;
        o4.x = cf * xv.x + df * hv.x;
        o4.y = cf * xv.y + df * hv.y;
        o4.z = cf * xv.z + df * hv.z;
        o4.w = cf * xv.w + df * hv.w;
        ((float4*)(out + row * D))[lane] = o4;
    }
}

// ---------------------------------------------------------------------------
extern "C" void kernel_launch(void* const* d_in, const int* in_sizes, int n_in,
                              void* d_out, int out_size) {
    const float* x   = (const float*)d_in[0];
    const float* adj = (const float*)d_in[1];
    const float* W_w = (const float*)d_in[2];
    const float* W_b = (const float*)d_in[3];
    const float* A   = (const float*)d_in[4];
    const float* gw  = (const float*)d_in[5];
    const float* gb  = (const float*)d_in[6];
    float* out = (float*)d_out;

    static bool attr_done = false;
    if (!attr_done) {
        cudaFuncSetAttribute(esym_k, cudaFuncAttributeMaxDynamicSharedMemorySize, SMEM_ESY);
        cudaFuncSetAttribute(hp_k,   cudaFuncAttributeMaxDynamicSharedMemorySize, SMEM_HP);
        attr_done = true;
    }

    prep_w_k<<<dim3(4, 4), dim3(32, 8)>>>(W_w);
    prep_m_k<<<dim3(4, 4), dim3(32, 8)>>>(A);
    fused_h_k<<<(B * N) / 32, 256>>>(x, W_b);
    esym_k<<<B * 136, NT, SMEM_ESY>>>(adj);
    scale_is_k<<<B * 32, 256>>>();
    hp_k<<<dim3(N / 128, B), NT, SMEM_HP>>>(x, gw, gb, out);
}

// round 17
// speedup vs baseline: 1.5788x; 1.2408x over previous
#include <cuda_runtime.h>
#include <cuda_bf16.h>
#include <cstdint>

namespace {
constexpr int B = 8;
constexpr int N = 2048;
constexpr int D = 128;
constexpr int LDS = 72;                    // padded smem row (bf16 elems)
constexpr int TILE_B = 128 * LDS * 2;      // 18432 bytes per operand tile
constexpr int STAGE_B = 4 * TILE_B;        // esym stage: Gh, Gl, hh, hl
constexpr int SMEM_ESY = 3 * STAGE_B;      // 221184
constexpr int STAGE_HP = 3 * TILE_B;       // hp stage: Uh, sh, sl
constexpr int SMEM_HP  = 4 * STAGE_HP;     // 221184 (4-stage)
constexpr int SMEM_FH  = 8 * TILE_B + 128 * 129 * 4;  // 213504
constexpr int ADJ_LDS = 132;               // fp32 elems per adj smem row
constexpr int NT = 512;                    // threads in MMA kernels
}

// ---------------------------------------------------------------------------
// Scratch (static device globals; no runtime allocation).
__device__ float g_hT[B * D * N];
__device__ float g_part[(size_t)B * N * 16];
__device__ __nv_bfloat16 g_Wh[D * D];
__device__ __nv_bfloat16 g_Wl[D * D];
__device__ __nv_bfloat16 g_Mh[D * D];      // splits of A + A^T (symmetric)
__device__ __nv_bfloat16 g_Ml[D * D];
__device__ __nv_bfloat16 g_hh[B * N * D];
__device__ __nv_bfloat16 g_hl[B * N * D];
__device__ __nv_bfloat16 g_Gh[B * N * D];  // splits of G = h.(A+A^T)
__device__ __nv_bfloat16 g_Gl[B * N * D];
__device__ __nv_bfloat16 g_sh[B * D * N];  // splits of is[j]*h^T
__device__ __nv_bfloat16 g_sl[B * D * N];
__device__ __nv_bfloat16 g_Uh[(size_t)B * N * N];  // bf16(masked exp(e_sym))

// ---------------------------------------------------------------------------
__device__ __forceinline__ uint32_t smem_u32(const void* p) {
    uint32_t a;
    asm("{ .reg .u64 t; cvta.to.shared.u64 t, %1; cvt.u32.u64 %0, t; }" : "=r"(a) : "l"(p));
    return a;
}
__device__ __forceinline__ void cp16(uint32_t dst, const void* src) {
    asm volatile("cp.async.cg.shared.global [%0], [%1], 16;" :: "r"(dst), "l"(src));
}
#define CP_COMMIT() asm volatile("cp.async.commit_group;" ::: "memory")
#define CP_WAIT(n)  asm volatile("cp.async.wait_group %0;" :: "n"(n) : "memory")

// 512-thread tile loader: 128x64 bf16 tile, 2 x 16B per thread.
__device__ __forceinline__ void issue_tile(uint32_t sdst,
                                           const __nv_bfloat16* __restrict__ base,
                                           size_t row0, int stride, int koff, int tid) {
#pragma unroll
    for (int t = 0; t < 2; t++) {
        const int i = t * NT + tid;
        const int rr = i >> 3, c16 = i & 7;
        cp16(sdst + (uint32_t)(rr * LDS + c16 * 8) * 2,
             base + (row0 + rr) * (size_t)stride + koff + c16 * 8);
    }
}

// 512-thread adj loader: 128x128 fp32 tile (row stride ADJ_LDS floats).
__device__ __forceinline__ void adj_issue(uint32_t sdst, const float* __restrict__ adjb,
                                          int r0, int c0, int tid) {
#pragma unroll
    for (int t = 0; t < 8; t++) {
        const int i = t * NT + tid;
        const int rr = i >> 5, cc = i & 31;
        cp16(sdst + (uint32_t)(rr * ADJ_LDS + cc * 4) * 4,
             adjb + (size_t)(r0 + rr) * N + c0 + cc * 4);
    }
    CP_COMMIT();
}

// ---------------------------------------------------------------------------
// Fragment loaders for the m16n8k16 layout. Warp tile 32(m) x 32(n).
__device__ __forceinline__ void lda_frag(uint32_t sA, int wr, int mi, int kk, int lane,
                                         uint32_t (&a)[4]) {
    const uint32_t addr = sA +
        ((wr * 32 + mi * 16 + (lane & 15)) * LDS + kk * 16 + ((lane >> 4) << 3)) * 2;
    asm volatile("ldmatrix.sync.aligned.m8n8.x4.shared.b16 {%0,%1,%2,%3}, [%4];"
                 : "=r"(a[0]), "=r"(a[1]), "=r"(a[2]), "=r"(a[3]) : "r"(addr));
}
__device__ __forceinline__ void ldb_frag4(uint32_t sB, int wc, int p, int kk, int lane,
                                          uint32_t (&b0)[2], uint32_t (&b1)[2]) {
    const uint32_t addr = sB +
        ((wc * 32 + (2 * p + ((lane >> 4) & 1)) * 8 + (lane & 7)) * LDS +
         kk * 16 + (((lane >> 3) & 1) << 3)) * 2;
    asm volatile("ldmatrix.sync.aligned.m8n8.x4.shared.b16 {%0,%1,%2,%3}, [%4];"
                 : "=r"(b0[0]), "=r"(b0[1]), "=r"(b1[0]), "=r"(b1[1]) : "r"(addr));
}
__device__ __forceinline__ void mma16816(float (&d)[4], const uint32_t (&a)[4],
                                         const uint32_t (&b)[2]) {
    asm volatile(
        "mma.sync.aligned.m16n8k16.row.col.f32.bf16.bf16.f32 "
        "{%0,%1,%2,%3}, {%4,%5,%6,%7}, {%8,%9}, {%0,%1,%2,%3};"
        : "+f"(d[0]), "+f"(d[1]), "+f"(d[2]), "+f"(d[3])
        : "r"(a[0]), "r"(a[1]), "r"(a[2]), "r"(a[3]), "r"(b[0]), "r"(b[1]));
}

// Three-term split MMA: acc += Ah.Bh + Ah.Bl + Al.Bh, software-pipelined.
__device__ __forceinline__ void mma_tri(uint32_t sAh, uint32_t sAl,
                                        uint32_t sBh, uint32_t sBl,
                                        int wr, int wc, int lane,
                                        float (&acc)[2][4][4]) {
    uint32_t ah[2][4], bh[4][2], ahn[2][4], bhn[4][2];
#pragma unroll
    for (int mi = 0; mi < 2; mi++) lda_frag(sAh, wr, mi, 0, lane, ah[mi]);
#pragma unroll
    for (int p = 0; p < 2; p++) ldb_frag4(sBh, wc, p, 0, lane, bh[2 * p], bh[2 * p + 1]);
#pragma unroll
    for (int kk = 0; kk < 4; kk++) {
        uint32_t al[2][4], bl[4][2];
#pragma unroll
        for (int p = 0; p < 2; p++) ldb_frag4(sBl, wc, p, kk, lane, bl[2 * p], bl[2 * p + 1]);
#pragma unroll
        for (int mi = 0; mi < 2; mi++) lda_frag(sAl, wr, mi, kk, lane, al[mi]);
        if (kk < 3) {
#pragma unroll
            for (int mi = 0; mi < 2; mi++) lda_frag(sAh, wr, mi, kk + 1, lane, ahn[mi]);
#pragma unroll
            for (int p = 0; p < 2; p++)
                ldb_frag4(sBh, wc, p, kk + 1, lane, bhn[2 * p], bhn[2 * p + 1]);
        }
#pragma unroll
        for (int mi = 0; mi < 2; mi++)
#pragma unroll
            for (int ni = 0; ni < 4; ni++) mma16816(acc[mi][ni], ah[mi], bh[ni]);
#pragma unroll
        for (int mi = 0; mi < 2; mi++)
#pragma unroll
            for (int ni = 0; ni < 4; ni++) mma16816(acc[mi][ni], ah[mi], bl[ni]);
#pragma unroll
        for (int mi = 0; mi < 2; mi++)
#pragma unroll
            for (int ni = 0; ni < 4; ni++) mma16816(acc[mi][ni], al[mi], bh[ni]);
        if (kk < 3) {
#pragma unroll
            for (int mi = 0; mi < 2; mi++)
#pragma unroll
                for (int q = 0; q < 4; q++) ah[mi][q] = ahn[mi][q];
#pragma unroll
            for (int ni = 0; ni < 4; ni++) {
                bh[ni][0] = bhn[ni][0];
                bh[ni][1] = bhn[ni][1];
            }
        }
    }
}

// Two-term split MMA (hp): acc += A.Bh + A.Bl, software-pipelined.
__device__ __forceinline__ void mma_duo(uint32_t sA, uint32_t sBh, uint32_t sBl,
                                        int wr, int wc, int lane,
                                        float (&acc)[2][4][4]) {
    uint32_t a[2][4], bh[4][2], an[2][4], bhn[4][2];
#pragma unroll
    for (int mi = 0; mi < 2; mi++) lda_frag(sA, wr, mi, 0, lane, a[mi]);
#pragma unroll
    for (int p = 0; p < 2; p++) ldb_frag4(sBh, wc, p, 0, lane, bh[2 * p], bh[2 * p + 1]);
#pragma unroll
    for (int kk = 0; kk < 4; kk++) {
        uint32_t bl[4][2];
#pragma unroll
        for (int p = 0; p < 2; p++) ldb_frag4(sBl, wc, p, kk, lane, bl[2 * p], bl[2 * p + 1]);
        if (kk < 3) {
#pragma unroll
            for (int mi = 0; mi < 2; mi++) lda_frag(sA, wr, mi, kk + 1, lane, an[mi]);
#pragma unroll
            for (int p = 0; p < 2; p++)
                ldb_frag4(sBh, wc, p, kk + 1, lane, bhn[2 * p], bhn[2 * p + 1]);
        }
#pragma unroll
        for (int mi = 0; mi < 2; mi++)
#pragma unroll
            for (int ni = 0; ni < 4; ni++) mma16816(acc[mi][ni], a[mi], bh[ni]);
#pragma unroll
        for (int mi = 0; mi < 2; mi++)
#pragma unroll
            for (int ni = 0; ni < 4; ni++) mma16816(acc[mi][ni], a[mi], bl[ni]);
        if (kk < 3) {
#pragma unroll
            for (int mi = 0; mi < 2; mi++)
#pragma unroll
                for (int q = 0; q < 4; q++) a[mi][q] = an[mi][q];
#pragma unroll
            for (int ni = 0; ni < 4; ni++) {
                bh[ni][0] = bhn[ni][0];
                bh[ni][1] = bhn[ni][1];
            }
        }
    }
}

__device__ __forceinline__ void acc_to_smem(float* sD, int wr, int wc, int lane,
                                            const float (&acc)[2][4][4], bool do_exp) {
#pragma unroll
    for (int mi = 0; mi < 2; mi++)
#pragma unroll
        for (int ni = 0; ni < 4; ni++) {
            const int row = wr * 32 + mi * 16 + (lane >> 2);
            const int col = wc * 32 + ni * 8 + (lane & 3) * 2;
            if (do_exp) {
                sD[row * 129 + col]           = __expf(acc[mi][ni][0]);
                sD[row * 129 + col + 1]       = __expf(acc[mi][ni][1]);
                sD[(row + 8) * 129 + col]     = __expf(acc[mi][ni][2]);
                sD[(row + 8) * 129 + col + 1] = __expf(acc[mi][ni][3]);
            } else {
                sD[row * 129 + col]           = acc[mi][ni][0];
                sD[row * 129 + col + 1]       = acc[mi][ni][1];
                sD[(row + 8) * 129 + col]     = acc[mi][ni][2];
                sD[(row + 8) * 129 + col + 1] = acc[mi][ni][3];
            }
        }
}

__device__ __forceinline__ uint32_t pack_bf16(float a, float b) {
    const __nv_bfloat16 ha = __float2bfloat16_rn(a);
    const __nv_bfloat16 hb = __float2bfloat16_rn(b);
    uint32_t r;
    asm("mov.b32 %0, {%1, %2};" : "=r"(r)
        : "h"(*(const uint16_t*)&ha), "h"(*(const uint16_t*)&hb));
    return r;
}
__device__ __forceinline__ uint32_t pack_lo(float a, float b) {
    const float ha = __bfloat162float(__float2bfloat16_rn(a));
    const float hb = __bfloat162float(__float2bfloat16_rn(b));
    return pack_bf16(a - ha, b - hb);
}

// ---------------------------------------------------------------------------
// Splits of W (elementwise) and M = A + A^T (symmetric).
__global__ void prep_k(const float* __restrict__ W, const float* __restrict__ A) {
    __shared__ float ta[32][33];
    const int bx = blockIdx.x, by = blockIdx.y;
    const int x = bx * 32 + threadIdx.x;
    const int y0 = by * 32;
    for (int i = threadIdx.y; i < 32; i += 8)
        ta[i][threadIdx.x] = A[(bx * 32 + i) * D + by * 32 + threadIdx.x];
    __syncthreads();
    for (int i = threadIdx.y; i < 32; i += 8) {
        const int o = (y0 + i) * D + x;
        const float w = W[o];
        const __nv_bfloat16 wh = __float2bfloat16_rn(w);
        g_Wh[o] = wh;
        g_Wl[o] = __float2bfloat16_rn(w - __bfloat162float(wh));
        const float m = A[o] + ta[threadIdx.x][i];
        const __nv_bfloat16 mh = __float2bfloat16_rn(m);
        g_Mh[o] = mh;
        g_Ml[o] = __float2bfloat16_rn(m - __bfloat162float(mh));
    }
}

// ---------------------------------------------------------------------------
// Tensorized front end. Per CTA (128 rows): h = x.W^T + b (3-term MMA),
// split h; G = h.M (3-term MMA, M symmetric); emit hh/hl/Gh/Gl/hT.
// SMEM: 8 operand tiles (A0h,A0l,B0h,B0l,A1h,A1l,B1h,B1l) + sH fp32 128x129.
__global__ void __launch_bounds__(NT) fused_h_k(const float* __restrict__ x,
                                                const float* __restrict__ bias) {
    extern __shared__ char sm[];
    const uint32_t sbase = smem_u32(sm);
    float* sH = (float*)(sm + 8 * TILE_B);
    const int tid = threadIdx.x, wid = tid >> 5, lane = tid & 31;
    const int wr = wid >> 2, wc = wid & 3;
    const int row0 = blockIdx.x * 128;
    const int b = row0 >> 11;
    const int n0 = row0 & (N - 1);

    // B tiles: W splits, chunks 0 and 1.
    issue_tile(sbase + 2 * TILE_B, g_Wh, 0, D, 0, tid);
    issue_tile(sbase + 3 * TILE_B, g_Wl, 0, D, 0, tid);
    issue_tile(sbase + 6 * TILE_B, g_Wh, 0, D, 64, tid);
    issue_tile(sbase + 7 * TILE_B, g_Wl, 0, D, 64, tid);
    CP_COMMIT();

    // A tiles: split x into chunk tiles (slots 0,1 and 4,5).
    const float4* xg = (const float4*)(x + (size_t)row0 * D);
#pragma unroll
    for (int i = tid; i < 4096; i += NT) {
        const int r = i >> 5, k4 = i & 31;
        const float4 v = xg[i];
        const int q = k4 >> 4;
        const int kin = (k4 & 15) * 4;
        const uint32_t off = (uint32_t)(r * LDS + kin) * 2;
        uint2 hh2, ll2;
        hh2.x = pack_bf16(v.x, v.y);
        hh2.y = pack_bf16(v.z, v.w);
        ll2.x = pack_lo(v.x, v.y);
        ll2.y = pack_lo(v.z, v.w);
        *(uint2*)(sm + (q * 4 + 0) * TILE_B + off) = hh2;
        *(uint2*)(sm + (q * 4 + 1) * TILE_B + off) = ll2;
    }

    float acc[2][4][4];
#pragma unroll
    for (int mi = 0; mi < 2; mi++)
#pragma unroll
        for (int ni = 0; ni < 4; ni++)
#pragma unroll
            for (int q = 0; q < 4; q++) acc[mi][ni][q] = 0.0f;

    CP_WAIT(0);
    __syncthreads();
    mma_tri(sbase, sbase + TILE_B, sbase + 2 * TILE_B, sbase + 3 * TILE_B,
            wr, wc, lane, acc);
    mma_tri(sbase + 4 * TILE_B, sbase + 5 * TILE_B, sbase + 6 * TILE_B,
            sbase + 7 * TILE_B, wr, wc, lane, acc);
    __syncthreads();   // all warps done with operand tiles

    // Prefetch M splits into B slots (overlaps the h epilogue below).
    issue_tile(sbase + 2 * TILE_B, g_Mh, 0, D, 0, tid);
    issue_tile(sbase + 3 * TILE_B, g_Ml, 0, D, 0, tid);
    issue_tile(sbase + 6 * TILE_B, g_Mh, 0, D, 64, tid);
    issue_tile(sbase + 7 * TILE_B, g_Ml, 0, D, 64, tid);
    CP_COMMIT();

    // h epilogue: +bias, sH, g_hh/g_hl; reset acc.
#pragma unroll
    for (int mi = 0; mi < 2; mi++)
#pragma unroll
        for (int ni = 0; ni < 4; ni++) {
            const int row = wr * 32 + mi * 16 + (lane >> 2);
            const int col = wc * 32 + ni * 8 + (lane & 3) * 2;
            const float b0 = bias[col], b1 = bias[col + 1];
            const float v0 = acc[mi][ni][0] + b0;
            const float v1 = acc[mi][ni][1] + b1;
            const float v2 = acc[mi][ni][2] + b0;
            const float v3 = acc[mi][ni][3] + b1;
            sH[row * 129 + col] = v0;
            sH[row * 129 + col + 1] = v1;
            sH[(row + 8) * 129 + col] = v2;
            sH[(row + 8) * 129 + col + 1] = v3;
            const size_t oA = ((size_t)(row0 + row) * D + col) >> 1;
            const size_t oB = ((size_t)(row0 + row + 8) * D + col) >> 1;
            ((uint32_t*)g_hh)[oA] = pack_bf16(v0, v1);
            ((uint32_t*)g_hl)[oA] = pack_lo(v0, v1);
            ((uint32_t*)g_hh)[oB] = pack_bf16(v2, v3);
            ((uint32_t*)g_hl)[oB] = pack_lo(v2, v3);
            acc[mi][ni][0] = 0.0f;
            acc[mi][ni][1] = 0.0f;
            acc[mi][ni][2] = 0.0f;
            acc[mi][ni][3] = 0.0f;
        }
    __syncthreads();   // sH complete

    // Split sH into A tiles (slots 0,1,4,5).
#pragma unroll
    for (int i = tid; i < 16384; i += NT) {
        const int r = i >> 7, k = i & 127;
        const float v = sH[r * 129 + k];
        const int q = k >> 6, kin = k & 63;
        const __nv_bfloat16 hi = __float2bfloat16_rn(v);
        const uint32_t off = (uint32_t)(r * LDS + kin) * 2;
        *(__nv_bfloat16*)(sm + (q * 4 + 0) * TILE_B + off) = hi;
        *(__nv_bfloat16*)(sm + (q * 4 + 1) * TILE_B + off) =
            __float2bfloat16_rn(v - __bfloat162float(hi));
    }
    CP_WAIT(0);
    __syncthreads();
    mma_tri(sbase, sbase + TILE_B, sbase + 2 * TILE_B, sbase + 3 * TILE_B,
            wr, wc, lane, acc);
    mma_tri(sbase + 4 * TILE_B, sbase + 5 * TILE_B, sbase + 6 * TILE_B,
            sbase + 7 * TILE_B, wr, wc, lane, acc);

    // G epilogue: g_Gh/g_Gl.
#pragma unroll
    for (int mi = 0; mi < 2; mi++)
#pragma unroll
        for (int ni = 0; ni < 4; ni++) {
            const int row = wr * 32 + mi * 16 + (lane >> 2);
            const int col = wc * 32 + ni * 8 + (lane & 3) * 2;
            const float v0 = acc[mi][ni][0], v1 = acc[mi][ni][1];
            const float v2 = acc[mi][ni][2], v3 = acc[mi][ni][3];
            const size_t oA = ((size_t)(row0 + row) * D + col) >> 1;
            const size_t oB = ((size_t)(row0 + row + 8) * D + col) >> 1;
            ((uint32_t*)g_Gh)[oA] = pack_bf16(v0, v1);
            ((uint32_t*)g_Gl)[oA] = pack_lo(v0, v1);
            ((uint32_t*)g_Gh)[oB] = pack_bf16(v2, v3);
            ((uint32_t*)g_Gl)[oB] = pack_lo(v2, v3);
        }

    // hT fp32 from sH.
    const int nn = tid & 127, d0 = tid >> 7;   // d0 0..3
#pragma unroll
    for (int dp = 0; dp < 32; dp++) {
        const int d = dp * 4 + d0;
        g_hT[((size_t)b * D + d) * N + n0 + nn] = sH[nn * 129 + d];
    }
}

// ---------------------------------------------------------------------------
// Esym = G.h^T (K=128, 2 chunks), 512 threads, upper-triangle tile pairs.
__device__ __forceinline__ void esym_issue(int q, int stage, uint32_t sbase,
                                           size_t arow, size_t brow, int tid) {
    const int koff = q * 64;
    const uint32_t s = sbase + (uint32_t)stage * STAGE_B;
    issue_tile(s,              g_Gh, arow, D, koff, tid);
    issue_tile(s + TILE_B,     g_Gl, arow, D, koff, tid);
    issue_tile(s + 2 * TILE_B, g_hh, brow, D, koff, tid);
    issue_tile(s + 3 * TILE_B, g_hl, brow, D, koff, tid);
    CP_COMMIT();
}

__global__ void __launch_bounds__(NT) esym_k(const float* __restrict__ adj) {
    extern __shared__ char sm[];
    const uint32_t sbase = smem_u32(sm);
    const int tid = threadIdx.x, wid = tid >> 5, lane = tid & 31;
    const int wr = wid >> 2, wc = wid & 3;

    int t = blockIdx.x % 136;
    const int b = blockIdx.x / 136;
    int tj = 0;
    while (t >= 16 - tj) { t -= 16 - tj; tj++; }
    const int tk = tj + t;
    const int j0 = tj * 128, k0 = tk * 128;
    const size_t arow = (size_t)b * N + j0, brow = (size_t)b * N + k0;
    const float* adjb = adj + (size_t)b * N * N;

    float acc[2][4][4];
#pragma unroll
    for (int mi = 0; mi < 2; mi++)
#pragma unroll
        for (int ni = 0; ni < 4; ni++)
#pragma unroll
            for (int q = 0; q < 4; q++) acc[mi][ni][q] = 0.0f;

    esym_issue(0, 0, sbase, arow, brow, tid);
    esym_issue(1, 1, sbase, arow, brow, tid);
    adj_issue(sbase + 2 * STAGE_B, adjb, j0, k0, tid);

    CP_WAIT(2); __syncthreads();
    mma_tri(sbase, sbase + TILE_B, sbase + 2 * TILE_B, sbase + 3 * TILE_B,
            wr, wc, lane, acc);
    __syncthreads();
    if (tj != tk) {
        adj_issue(sbase, adjb, k0, j0, tid);
        CP_WAIT(2);
    } else {
        CP_WAIT(1);
    }
    __syncthreads();
    {
        const uint32_t s = sbase + STAGE_B;
        mma_tri(s, s + TILE_B, s + 2 * TILE_B, s + 3 * TILE_B, wr, wc, lane, acc);
    }
    CP_WAIT(0);
    __syncthreads();

    float* sD   = (float*)(sm + STAGE_B);
    float* sA1  = (float*)(sm + 2 * STAGE_B);
    float* sA2  = (float*)sm;
    float* red1 = (float*)(sm + 67584);
    float* red2 = (float*)(sm + STAGE_B + 66048);
    acc_to_smem(sD, wr, wc, lane, acc, true);
    __syncthreads();

    const int c2 = (tid & 63) * 2;
    const int p = tid >> 6;
    {
        float cs0 = 0.0f, cs1 = 0.0f;
        const size_t ub = (size_t)b * N * N + (size_t)j0 * N + k0;
#pragma unroll 8
        for (int it = 0; it < 16; it++) {
            const int r = it * 8 + p;
            const float v0 = (sA1[r * ADJ_LDS + c2] > 0.0f) ? sD[r * 129 + c2] : 0.0f;
            const float v1 = (sA1[r * ADJ_LDS + c2 + 1] > 0.0f) ? sD[r * 129 + c2 + 1] : 0.0f;
            ((uint32_t*)g_Uh)[(ub + (size_t)r * N + c2) >> 1] = pack_bf16(v0, v1);
            cs0 += v0;
            cs1 += v1;
        }
        red1[c2 * 8 + p] = cs0;
        red1[(c2 + 1) * 8 + p] = cs1;
    }
    if (tj != tk) {
        float cs0 = 0.0f, cs1 = 0.0f;
        const size_t ub = (size_t)b * N * N + (size_t)k0 * N + j0;
#pragma unroll 8
        for (int it = 0; it < 16; it++) {
            const int r = it * 8 + p;
            const float v0 = (sA2[r * ADJ_LDS + c2] > 0.0f) ? sD[c2 * 129 + r] : 0.0f;
            const float v1 = (sA2[r * ADJ_LDS + c2 + 1] > 0.0f) ? sD[(c2 + 1) * 129 + r] : 0.0f;
            ((uint32_t*)g_Uh)[(ub + (size_t)r * N + c2) >> 1] = pack_bf16(v0, v1);
            cs0 += v0;
            cs1 += v1;
        }
        red2[c2 * 8 + p] = cs0;
        red2[(c2 + 1) * 8 + p] = cs1;
    }
    __syncthreads();
    if (tid < 128) {
        float s = 0.0f;
#pragma unroll
        for (int q = 0; q < 8; q++) s += red1[tid * 8 + q];
        g_part[((size_t)b * N + k0 + tid) * 16 + tj] = s;
    } else if (tid < 256 && tj != tk) {
        const int cc = tid - 128;
        float s = 0.0f;
#pragma unroll
        for (int q = 0; q < 8; q++) s += red2[cc * 8 + q];
        g_part[((size_t)b * N + j0 + cc) * 16 + tk] = s;
    }
}

// ---------------------------------------------------------------------------
// Per block: reduce is[] for 256 columns (16 slots each), scale 32 d-rows.
__global__ void __launch_bounds__(256) scale_is_k() {
    __shared__ float s_is[256];
    const int bx = blockIdx.x;
    const int b = bx >> 5;
    const int rem = bx & 31;
    const int j0 = (rem & 7) * 256;
    const int d0 = (rem >> 3) * 32;
    const int tid = threadIdx.x;

    {
        const float4* p = (const float4*)(g_part + ((size_t)b * N + j0 + tid) * 16);
        float s = 0.0f;
#pragma unroll
        for (int q = 0; q < 4; q++) {
            const float4 v = p[q];
            s += (v.x + v.y) + (v.z + v.w);
        }
        s_is[tid] = 1.0f / s;
    }
    __syncthreads();

    const int jq = tid & 63, dr0 = tid >> 6;
    const float4 sv = ((const float4*)s_is)[jq];
#pragma unroll
    for (int it = 0; it < 8; it++) {
        const int d = d0 + it * 4 + dr0;
        const size_t o4 = (((size_t)b * D + d) * N + j0) / 4 + jq;
        const float4 hv = ((const float4*)g_hT)[o4];
        const float v0 = hv.x * sv.x, v1 = hv.y * sv.y, v2 = hv.z * sv.z, v3 = hv.w * sv.w;
        uint2 ph, pl;
        ph.x = pack_bf16(v0, v1);
        ph.y = pack_bf16(v2, v3);
        pl.x = pack_lo(v0, v1);
        pl.y = pack_lo(v2, v3);
        ((uint2*)g_sh)[o4] = ph;
        ((uint2*)g_sl)[o4] = pl;
    }
}

// ---------------------------------------------------------------------------
// hp+gate fused: 2-term (Uh.sh + Uh.sl), 4 stages, depth-3 prefetch.
__device__ __forceinline__ void hp_issue(int c, int stage, uint32_t sbase,
                                         size_t arow, size_t brow, int tid) {
    const int koff = c * 64;
    const uint32_t s = sbase + (uint32_t)stage * STAGE_HP;
    issue_tile(s,              g_Uh, arow, N, koff, tid);
    issue_tile(s + TILE_B,     g_sh, brow, N, koff, tid);
    issue_tile(s + 2 * TILE_B, g_sl, brow, N, koff, tid);
    CP_COMMIT();
}

__global__ void __launch_bounds__(NT) hp_k(
    const float* __restrict__ x, const float* __restrict__ gw,
    const float* __restrict__ gb, float* __restrict__ out) {
    extern __shared__ char sm[];
    const uint32_t sbase = smem_u32(sm);
    const int tid = threadIdx.x, wid = tid >> 5, lane = tid & 31;
    const int wr = wid >> 2, wc = wid & 3;
    const int b = blockIdx.y;
    const int i0 = blockIdx.x * 128;
    const size_t arow = (size_t)b * N + i0;
    const size_t brow = (size_t)b * D;

    float acc[2][4][4];
#pragma unroll
    for (int mi = 0; mi < 2; mi++)
#pragma unroll
        for (int ni = 0; ni < 4; ni++)
#pragma unroll
            for (int q = 0; q < 4; q++) acc[mi][ni][q] = 0.0f;

    hp_issue(0, 0, sbase, arow, brow, tid);
    hp_issue(1, 1, sbase, arow, brow, tid);
    hp_issue(2, 2, sbase, arow, brow, tid);
#pragma unroll 1
    for (int c = 0; c < 32; c++) {
        if (c < 30) CP_WAIT(2);
        else if (c == 30) CP_WAIT(1);
        else CP_WAIT(0);
        __syncthreads();
        if (c + 3 < 32) hp_issue(c + 3, (c + 3) & 3, sbase, arow, brow, tid);
        const uint32_t s = sbase + (uint32_t)(c & 3) * STAGE_HP;
        mma_duo(s, s + TILE_B, s + 2 * TILE_B, wr, wc, lane, acc);
    }
    __syncthreads();

    float* sD = (float*)sm;
    acc_to_smem(sD, wr, wc, lane, acc, false);
    __syncthreads();

    const float4 g1 = ((const float4*)gw)[lane];
    const float4 g2 = ((const float4*)(gw + D))[lane];
    const float gbv = gb[0];
#pragma unroll 1
    for (int rr = wid; rr < 128; rr += 16) {
        const size_t row = (size_t)b * N + i0 + rr;
        const float4 xv = ((const float4*)(x + row * D))[lane];
        float4 hv;
        hv.x = fmaxf(sD[rr * 129 + lane * 4 + 0], 0.0f);
        hv.y = fmaxf(sD[rr * 129 + lane * 4 + 1], 0.0f);
        hv.z = fmaxf(sD[rr * 129 + lane * 4 + 2], 0.0f);
        hv.w = fmaxf(sD[rr * 129 + lane * 4 + 3], 0.0f);
        float p = xv.x * g1.x + xv.y * g1.y + xv.z * g1.z + xv.w * g1.w
                + hv.x * g2.x + hv.y * g2.y + hv.z * g2.z + hv.w * g2.w;
#pragma unroll
        for (int o = 16; o > 0; o >>= 1) p += __shfl_xor_sync(0xffffffffu, p, o);
        const float cf = 1.0f / (1.0f + __expf(-(p + gbv)));
        const float df = 1.0f - cf;
        float4 o4;
        o4.x = cf * xv.x + df * hv.x;
        o4.y = cf * xv.y + df * hv.y;
        o4.z = cf * xv.z + df * hv.z;
        o4.w = cf * xv.w + df * hv.w;
        ((float4*)(out + row * D))[lane] = o4;
    }
}

// ---------------------------------------------------------------------------
extern "C" void kernel_launch(void* const* d_in, const int* in_sizes, int n_in,
                              void* d_out, int out_size) {
    const float* x   = (const float*)d_in[0];
    const float* adj = (const float*)d_in[1];
    const float* W_w = (const float*)d_in[2];
    const float* W_b = (const float*)d_in[3];
    const float* A   = (const float*)d_in[4];
    const float* gw  = (const float*)d_in[5];
    const float* gb  = (const float*)d_in[6];
    float* out = (float*)d_out;

    static bool attr_done = false;
    if (!attr_done) {
        cudaFuncSetAttribute(fused_h_k, cudaFuncAttributeMaxDynamicSharedMemorySize, SMEM_FH);
        cudaFuncSetAttribute(esym_k, cudaFuncAttributeMaxDynamicSharedMemorySize, SMEM_ESY);
        cudaFuncSetAttribute(hp_k,   cudaFuncAttributeMaxDynamicSharedMemorySize, SMEM_HP);
        attr_done = true;
    }

    prep_k<<<dim3(4, 4), dim3(32, 8)>>>(W_w, A);
    fused_h_k<<<(B * N) / 128, NT, SMEM_FH>>>(x, W_b);
    esym_k<<<B * 136, NT, SMEM_ESY>>>(adj);
    scale_is_k<<<B * 32, 256>>>();
    hp_k<<<dim3(N / 128, B), NT, SMEM_HP>>>(x, gw, gb, out);
}